// round 4
// baseline (speedup 1.0000x reference)
#include <cuda_runtime.h>
#include <cuda_bf16.h>
#include <math.h>
#include <stdint.h>

#define NROW 8192
#define DIM  256

// ---------------- scratch (no cudaMalloc allowed) ----------------
static __device__ __nv_bfloat16 g_Uhi [(size_t)NROW * NROW];   // 128 MB  exp(W-10) hi
static __device__ __nv_bfloat16 g_Ulo [(size_t)NROW * NROW];   // 128 MB  exp(W-10) lo
static __device__ float         g_psum[(size_t)64 * NROW];     // per-N-tile row sums
static __device__ float         g_rinv[NROW];                  // 1/rowsum
static __device__ __nv_bfloat16 g_Ehi [(size_t)NROW * DIM];
static __device__ __nv_bfloat16 g_Elo [(size_t)NROW * DIM];
static __device__ __nv_bfloat16 g_Vthi[(size_t)DIM * NROW];
static __device__ __nv_bfloat16 g_Vtlo[(size_t)DIM * NROW];

// ---------------- portable PTX helpers (sm_80+ only) ----------------
__device__ __forceinline__ uint32_t smem_u32(const void* p) {
    return (uint32_t)__cvta_generic_to_shared(p);
}
__device__ __forceinline__ void cp16(uint32_t dst, const void* src) {
    asm volatile("cp.async.cg.shared.global [%0], [%1], 16;"
                 :: "r"(dst), "l"(src) : "memory");
}
__device__ __forceinline__ void cp_commit() {
    asm volatile("cp.async.commit_group;" ::: "memory");
}
template <int N> __device__ __forceinline__ void cp_wait() {
    asm volatile("cp.async.wait_group %0;" :: "n"(N) : "memory");
}
__device__ __forceinline__ void ldsm4(uint32_t& r0, uint32_t& r1,
                                      uint32_t& r2, uint32_t& r3, uint32_t addr) {
    asm volatile("ldmatrix.sync.aligned.m8n8.x4.shared.b16 {%0,%1,%2,%3}, [%4];"
                 : "=r"(r0), "=r"(r1), "=r"(r2), "=r"(r3) : "r"(addr));
}
__device__ __forceinline__ void mma16816(float* d,
                                         uint32_t a0, uint32_t a1, uint32_t a2, uint32_t a3,
                                         uint32_t b0, uint32_t b1) {
    asm volatile("mma.sync.aligned.m16n8k16.row.col.f32.bf16.bf16.f32 "
                 "{%0,%1,%2,%3},{%4,%5,%6,%7},{%8,%9},{%0,%1,%2,%3};"
                 : "+f"(d[0]), "+f"(d[1]), "+f"(d[2]), "+f"(d[3])
                 : "r"(a0), "r"(a1), "r"(a2), "r"(a3), "r"(b0), "r"(b1));
}

// ---------------------------------------------------------------------------
// fast exp on the FMA pipe (avoids MUFU.EX2 wall at 67M exps).
// ---------------------------------------------------------------------------
__device__ __forceinline__ float fast_exp(float x)
{
    float t = x * 1.4426950408889634f;
    t = fmaxf(t, -126.0f);
    float fi = floorf(t);
    float f  = t - fi;
    float p = 1.5403530393381608e-4f;
    p = fmaf(p, f, 1.3333558146428443e-3f);
    p = fmaf(p, f, 9.6181291076284770e-3f);
    p = fmaf(p, f, 5.5504108664821580e-2f);
    p = fmaf(p, f, 2.4022650695910070e-1f);
    p = fmaf(p, f, 6.9314718055994530e-1f);
    p = fmaf(p, f, 1.0f);
    return p * __int_as_float(((int)fi + 127) << 23);
}

// ---------------------------------------------------------------------------
// K1: normalize rows (fold 1/sqrt(sigma)), split into bf16 hi/lo.
// ---------------------------------------------------------------------------
__device__ __forceinline__ void split4(__nv_bfloat16* hi, __nv_bfloat16* lo,
                                       size_t idx, float4 v)
{
    __nv_bfloat16 h0 = __float2bfloat16(v.x), h1 = __float2bfloat16(v.y);
    __nv_bfloat16 h2 = __float2bfloat16(v.z), h3 = __float2bfloat16(v.w);
    __nv_bfloat16 l0 = __float2bfloat16(v.x - __bfloat162float(h0));
    __nv_bfloat16 l1 = __float2bfloat16(v.y - __bfloat162float(h1));
    __nv_bfloat16 l2 = __float2bfloat16(v.z - __bfloat162float(h2));
    __nv_bfloat16 l3 = __float2bfloat16(v.w - __bfloat162float(h3));
    *(__nv_bfloat162*)(hi + idx)     = __halves2bfloat162(h0, h1);
    *(__nv_bfloat162*)(hi + idx + 2) = __halves2bfloat162(h2, h3);
    *(__nv_bfloat162*)(lo + idx)     = __halves2bfloat162(l0, l1);
    *(__nv_bfloat162*)(lo + idx + 2) = __halves2bfloat162(l2, l3);
}

__global__ void k_normalize(const float* __restrict__ emb)
{
    int row  = blockIdx.x * 4 + (threadIdx.x >> 5);
    int lane = threadIdx.x & 31;
    const float4* src = (const float4*)(emb + (size_t)row * DIM);
    float4 v0 = src[lane];
    float4 v1 = src[lane + 32];
    float s = v0.x*v0.x + v0.y*v0.y + v0.z*v0.z + v0.w*v0.w
            + v1.x*v1.x + v1.y*v1.y + v1.z*v1.z + v1.w*v1.w;
    #pragma unroll
    for (int o = 16; o; o >>= 1) s += __shfl_xor_sync(0xFFFFFFFFu, s, o);
    float nrm = fmaxf(sqrtf(s), 1e-12f);
    float scale = 1.0f / (nrm * 0.316227766016838f);   // 1/(norm*sqrt(sigma))
    v0.x *= scale; v0.y *= scale; v0.z *= scale; v0.w *= scale;
    v1.x *= scale; v1.y *= scale; v1.z *= scale; v1.w *= scale;
    size_t base = (size_t)row * DIM;
    split4(g_Ehi, g_Elo, base + lane * 4,        v0);
    split4(g_Ehi, g_Elo, base + (lane + 32) * 4, v1);
}

// ---------------------------------------------------------------------------
// K2: tiled transpose + split of V = emb_org -> Vt[c][r] (bf16 hi/lo).
// ---------------------------------------------------------------------------
__global__ void k_transpose_split(const float* __restrict__ emb)
{
    __shared__ float t[32][33];
    int r0 = blockIdx.x * 32;
    int c0 = blockIdx.y * 32;
    int tx = threadIdx.x, ty = threadIdx.y;   // 32 x 8
    #pragma unroll
    for (int i = 0; i < 32; i += 8)
        t[ty + i][tx] = emb[(size_t)(r0 + ty + i) * DIM + c0 + tx];
    __syncthreads();
    #pragma unroll
    for (int i = 0; i < 32; i += 8) {
        float v = t[tx][ty + i];
        __nv_bfloat16 h = __float2bfloat16(v);
        size_t idx = (size_t)(c0 + ty + i) * NROW + r0 + tx;
        g_Vthi[idx] = h;
        g_Vtlo[idx] = __float2bfloat16(v - __bfloat162float(h));
    }
}

// ---------------------------------------------------------------------------
// Shared MMA: warp tile (MI*16) x 32, k-chunk 64, permuted smem layout.
// ---------------------------------------------------------------------------
template<int MI>
__device__ __forceinline__ void tile_mma_t(float (&acc)[MI][4][4], int lane,
                                           int wm, int wn,
                                           uint32_t abase, uint32_t bbase)
{
    #pragma unroll
    for (int kk = 0; kk < 4; kk++) {
        uint32_t a[MI][4];
        #pragma unroll
        for (int mi = 0; mi < MI; mi++) {
            int row = wm + mi * 16 + (lane & 15);
            int k16 = 2 * kk + (lane >> 4);
            ldsm4(a[mi][0], a[mi][1], a[mi][2], a[mi][3],
                  abase + row * 128 + ((k16 ^ (row & 7)) << 4));
        }
        #pragma unroll
        for (int jb = 0; jb < 2; jb++) {
            uint32_t b[4];
            int row = wn + jb * 16 + (lane & 7) + ((lane >> 4) << 3);
            int k16 = 2 * kk + ((lane >> 3) & 1);
            ldsm4(b[0], b[1], b[2], b[3],
                  bbase + row * 128 + ((k16 ^ (row & 7)) << 4));
            #pragma unroll
            for (int mi = 0; mi < MI; mi++) {
                mma16816(acc[mi][jb * 2 + 0], a[mi][0], a[mi][1], a[mi][2], a[mi][3], b[0], b[1]);
                mma16816(acc[mi][jb * 2 + 1], a[mi][0], a[mi][1], a[mi][2], a[mi][3], b[2], b[3]);
            }
        }
    }
}

// ---------------------------------------------------------------------------
// K3: GEMM-S + fused exp epilogue.
// 128x128 CTA tile, 8 warps (2m x 4n), warp 64x32. 2-stage cp.async.
// Writes U = exp(W-10) as bf16 hi/lo (smem-staged coalesced) + row-sum
// partials to g_psum[bn_tile][row] (deterministic, no atomics).
// ---------------------------------------------------------------------------
#define SMSTAGE 32768

__device__ __forceinline__ void s_load(const __nv_bfloat16* __restrict__ Asrc,
                                       const __nv_bfloat16* __restrict__ Bsrc,
                                       size_t k0, int bm0, int bn0, int tid,
                                       uint32_t stbase)
{
    uint32_t abase = stbase, bbase = stbase + 16384;
    #pragma unroll
    for (int q = 0; q < 4; q++) {
        int v = tid + q * 256;
        int row = v >> 3, k16 = v & 7;
        uint32_t off = row * 128 + ((k16 ^ (row & 7)) << 4);
        cp16(abase + off, Asrc + (size_t)(bm0 + row) * DIM + k0 + k16 * 8);
        cp16(bbase + off, Bsrc + (size_t)(bn0 + row) * DIM + k0 + k16 * 8);
    }
    cp_commit();
}

__global__ __launch_bounds__(256, 2) void k_gemm_s()
{
    extern __shared__ __align__(1024) char dsm[];
    uint32_t dynb = smem_u32(dsm);
    int tid = threadIdx.x, lane = tid & 31, wid = tid >> 5;
    int wm = (wid >> 2) * 64, wn = (wid & 3) * 32;
    int bm0 = blockIdx.y * 128, bn0 = blockIdx.x * 128;

    float acc[4][4][4];
    #pragma unroll
    for (int i = 0; i < 4; i++)
        #pragma unroll
        for (int j = 0; j < 4; j++)
            #pragma unroll
            for (int q = 0; q < 4; q++) acc[i][j][q] = 0.0f;

    const int NIT = 12;   // (hi*hi, hi*lo, lo*hi) x 4 chunks of 64
    s_load(g_Ehi, g_Ehi, 0, bm0, bn0, tid, dynb);
    for (int it = 0; it < NIT; it++) {
        int s = it & 1;
        int nx = it + 1;
        if (nx < NIT) {
            int pass = nx >> 2, ch = nx & 3;
            const __nv_bfloat16* As = (pass == 2) ? g_Elo : g_Ehi;
            const __nv_bfloat16* Bs = (pass == 1) ? g_Elo : g_Ehi;
            s_load(As, Bs, (size_t)ch * 64, bm0, bn0, tid, dynb + (nx & 1) * SMSTAGE);
            cp_wait<1>();
        } else {
            cp_wait<0>();
        }
        __syncthreads();
        uint32_t base = dynb + s * SMSTAGE;
        tile_mma_t<4>(acc, lane, wm, wn, base, base + 16384);
        __syncthreads();
    }

    // ---- fused epilogue: U = exp(W - 10), row sums, bf16 hi/lo store ----
    int g = lane >> 2, c2 = (lane & 3) * 2;

    float pa[4], pb[4];
    #pragma unroll
    for (int mi = 0; mi < 4; mi++) { pa[mi] = 0.0f; pb[mi] = 0.0f; }
    #pragma unroll
    for (int mi = 0; mi < 4; mi++)
        #pragma unroll
        for (int nj = 0; nj < 4; nj++) {
            #pragma unroll
            for (int q = 0; q < 4; q++)
                acc[mi][nj][q] = fast_exp(acc[mi][nj][q] - 10.0f);
            pa[mi] += acc[mi][nj][0] + acc[mi][nj][1];
            pb[mi] += acc[mi][nj][2] + acc[mi][nj][3];
        }

    // quad-reduce (4 lanes share a row), deterministic slot store per n-warp
    float* ssum = (float*)dsm;   // [4][128]
    #pragma unroll
    for (int mi = 0; mi < 4; mi++) {
        pa[mi] += __shfl_xor_sync(0xFFFFFFFFu, pa[mi], 1);
        pa[mi] += __shfl_xor_sync(0xFFFFFFFFu, pa[mi], 2);
        pb[mi] += __shfl_xor_sync(0xFFFFFFFFu, pb[mi], 1);
        pb[mi] += __shfl_xor_sync(0xFFFFFFFFu, pb[mi], 2);
        if ((lane & 3) == 0) {
            int rl = wm + mi * 16 + g;
            ssum[(wid & 3) * 128 + rl]     = pa[mi];
            ssum[(wid & 3) * 128 + rl + 8] = pb[mi];
        }
    }
    __syncthreads();
    if (tid < 128)
        g_psum[(size_t)blockIdx.x * NROW + bm0 + tid] =
            ssum[tid] + ssum[128 + tid] + ssum[256 + tid] + ssum[384 + tid];
    __syncthreads();

    // smem-staged coalesced stores (stride 136 kills bank conflicts)
    __nv_bfloat16* s16 = (__nv_bfloat16*)dsm;
    // round 0: hi
    #pragma unroll
    for (int mi = 0; mi < 4; mi++)
        #pragma unroll
        for (int nj = 0; nj < 4; nj++) {
            int rl = wm + mi * 16 + g, col = wn + nj * 8 + c2;
            *(__nv_bfloat162*)&s16[rl * 136 + col] =
                __halves2bfloat162(__float2bfloat16(acc[mi][nj][0]),
                                   __float2bfloat16(acc[mi][nj][1]));
            *(__nv_bfloat162*)&s16[(rl + 8) * 136 + col] =
                __halves2bfloat162(__float2bfloat16(acc[mi][nj][2]),
                                   __float2bfloat16(acc[mi][nj][3]));
        }
    __syncthreads();
    {
        int rr = tid >> 1, hh = tid & 1;
        #pragma unroll
        for (int j = 0; j < 8; j++) {
            uint4 v = *(uint4*)&s16[rr * 136 + hh * 64 + j * 8];
            *(uint4*)&g_Uhi[(size_t)(bm0 + rr) * NROW + bn0 + hh * 64 + j * 8] = v;
        }
    }
    __syncthreads();
    // round 1: lo
    #pragma unroll
    for (int mi = 0; mi < 4; mi++)
        #pragma unroll
        for (int nj = 0; nj < 4; nj++) {
            int rl = wm + mi * 16 + g, col = wn + nj * 8 + c2;
            float l0 = acc[mi][nj][0] - __bfloat162float(__float2bfloat16(acc[mi][nj][0]));
            float l1 = acc[mi][nj][1] - __bfloat162float(__float2bfloat16(acc[mi][nj][1]));
            float l2 = acc[mi][nj][2] - __bfloat162float(__float2bfloat16(acc[mi][nj][2]));
            float l3 = acc[mi][nj][3] - __bfloat162float(__float2bfloat16(acc[mi][nj][3]));
            *(__nv_bfloat162*)&s16[rl * 136 + col] =
                __halves2bfloat162(__float2bfloat16(l0), __float2bfloat16(l1));
            *(__nv_bfloat162*)&s16[(rl + 8) * 136 + col] =
                __halves2bfloat162(__float2bfloat16(l2), __float2bfloat16(l3));
        }
    __syncthreads();
    {
        int rr = tid >> 1, hh = tid & 1;
        #pragma unroll
        for (int j = 0; j < 8; j++) {
            uint4 v = *(uint4*)&s16[rr * 136 + hh * 64 + j * 8];
            *(uint4*)&g_Ulo[(size_t)(bm0 + rr) * NROW + bn0 + hh * 64 + j * 8] = v;
        }
    }
}

// ---------------------------------------------------------------------------
// K4: reduce per-tile row sums -> 1/s_i.
// ---------------------------------------------------------------------------
__global__ void k_rowinv()
{
    int r = blockIdx.x * 256 + threadIdx.x;
    float s = 0.0f;
    #pragma unroll 8
    for (int t = 0; t < 64; t++) s += g_psum[(size_t)t * NROW + r];
    g_rinv[r] = 1.0f / s;
}

// ---------------------------------------------------------------------------
// K5: O = (U @ V) * rinv, merged split-bf16 (3 products / k-chunk).
// CTA tile 64(m) x 128(n), grid (2, 128) = 256 CTAs. 8 warps (2m x 4n),
// warp 32x32. Stage = Uhi 8K | Ulo 8K | Vhi 16K | Vlo 16K = 48KB, 2 stages.
// ---------------------------------------------------------------------------
#define OSTG 49152

__device__ __forceinline__ void o_load(int it, int bm0, int bn0, int tid,
                                       uint32_t base)
{
    size_t k0 = (size_t)it * 64;
    const __nv_bfloat16* th = g_Uhi  + (size_t)bm0 * NROW + k0;
    const __nv_bfloat16* tl = g_Ulo  + (size_t)bm0 * NROW + k0;
    const __nv_bfloat16* vh = g_Vthi + (size_t)bn0 * NROW + k0;
    const __nv_bfloat16* vl = g_Vtlo + (size_t)bn0 * NROW + k0;
    #pragma unroll
    for (int q = 0; q < 2; q++) {
        int v = tid + q * 256;
        int row = v >> 3, k16 = v & 7;
        uint32_t off = row * 128 + ((k16 ^ (row & 7)) << 4);
        cp16(base + off,        th + (size_t)row * NROW + k16 * 8);
        cp16(base + 8192 + off, tl + (size_t)row * NROW + k16 * 8);
    }
    #pragma unroll
    for (int q = 0; q < 4; q++) {
        int v = tid + q * 256;
        int row = v >> 3, k16 = v & 7;
        uint32_t off = row * 128 + ((k16 ^ (row & 7)) << 4);
        cp16(base + 16384 + off, vh + (size_t)row * NROW + k16 * 8);
        cp16(base + 32768 + off, vl + (size_t)row * NROW + k16 * 8);
    }
    cp_commit();
}

__global__ __launch_bounds__(256, 2) void k_gemm_o(float* __restrict__ C)
{
    extern __shared__ __align__(1024) char dsm[];
    uint32_t dynb = smem_u32(dsm);
    int tid = threadIdx.x, lane = tid & 31, wid = tid >> 5;
    int wm = (wid >> 2) * 32, wn = (wid & 3) * 32;
    int bm0 = blockIdx.y * 64, bn0 = blockIdx.x * 128;

    float acc[2][4][4];
    #pragma unroll
    for (int i = 0; i < 2; i++)
        #pragma unroll
        for (int j = 0; j < 4; j++)
            #pragma unroll
            for (int q = 0; q < 4; q++) acc[i][j][q] = 0.0f;

    const int NIT = 128;
    o_load(0, bm0, bn0, tid, dynb);

    #pragma unroll 1
    for (int it = 0; it < NIT; it++) {
        int s = it & 1;
        if (it + 1 < NIT) {
            o_load(it + 1, bm0, bn0, tid, dynb + ((it + 1) & 1) * OSTG);
            cp_wait<1>();
        } else {
            cp_wait<0>();
        }
        __syncthreads();
        uint32_t base = dynb + s * OSTG;
        tile_mma_t<2>(acc, lane, wm, wn, base,        base + 16384);  // Uhi*Vhi
        tile_mma_t<2>(acc, lane, wm, wn, base,        base + 32768);  // Uhi*Vlo
        tile_mma_t<2>(acc, lane, wm, wn, base + 8192, base + 16384);  // Ulo*Vhi
        __syncthreads();
    }

    int g = lane >> 2, c2 = (lane & 3) * 2;
    #pragma unroll
    for (int mi = 0; mi < 2; mi++) {
        int ra = bm0 + wm + mi * 16 + g;
        float ia = g_rinv[ra], ib = g_rinv[ra + 8];
        #pragma unroll
        for (int nj = 0; nj < 4; nj++) {
            int col = bn0 + wn + nj * 8 + c2;
            *(float2*)&C[(size_t)ra * DIM + col] =
                make_float2(acc[mi][nj][0] * ia, acc[mi][nj][1] * ia);
            *(float2*)&C[(size_t)(ra + 8) * DIM + col] =
                make_float2(acc[mi][nj][2] * ib, acc[mi][nj][3] * ib);
        }
    }
}

// ---------------------------------------------------------------------------
extern "C" void kernel_launch(void* const* d_in, const int* in_sizes, int n_in,
                              void* d_out, int out_size)
{
    const float* emb = (const float*)d_in[0];
    float* out = (float*)d_out;

    cudaFuncSetAttribute(k_gemm_s, cudaFuncAttributeMaxDynamicSharedMemorySize, 2 * SMSTAGE);
    cudaFuncSetAttribute(k_gemm_o, cudaFuncAttributeMaxDynamicSharedMemorySize, 2 * OSTG);

    k_normalize<<<NROW / 4, 128>>>(emb);

    dim3 tb(32, 8);
    k_transpose_split<<<dim3(NROW / 32, DIM / 32), tb>>>(emb);

    k_gemm_s<<<dim3(NROW / 128, NROW / 128), 256, 2 * SMSTAGE>>>();

    k_rowinv<<<NROW / 256, 256>>>();

    k_gemm_o<<<dim3(DIM / 128, NROW / 64), 256, 2 * OSTG>>>(out);
}

// round 5
// speedup vs baseline: 2.3153x; 2.3153x over previous
#include <cuda_runtime.h>
#include <cuda_fp16.h>
#include <math.h>
#include <stdint.h>

#define NROW 8192
#define DIM  256

// ---------------- scratch (no cudaMalloc allowed) ----------------
static __device__ __half g_U   [(size_t)NROW * NROW];   // 128 MB  exp(W-3) fp16
static __device__ float  g_psum[(size_t)64 * NROW];     // per-N-tile row sums
static __device__ float  g_rinv[NROW];                  // 1/rowsum
static __device__ __half g_Eh  [(size_t)NROW * DIM];    // normalized emb / sqrt(sigma)
static __device__ __half g_Vt  [(size_t)DIM * NROW];    // emb_org^T

// ---------------- portable PTX helpers (sm_80+ only) ----------------
__device__ __forceinline__ uint32_t smem_u32(const void* p) {
    return (uint32_t)__cvta_generic_to_shared(p);
}
__device__ __forceinline__ void cp16(uint32_t dst, const void* src) {
    asm volatile("cp.async.cg.shared.global [%0], [%1], 16;"
                 :: "r"(dst), "l"(src) : "memory");
}
__device__ __forceinline__ void cp_commit() {
    asm volatile("cp.async.commit_group;" ::: "memory");
}
template <int N> __device__ __forceinline__ void cp_wait() {
    asm volatile("cp.async.wait_group %0;" :: "n"(N) : "memory");
}
__device__ __forceinline__ void ldsm4(uint32_t& r0, uint32_t& r1,
                                      uint32_t& r2, uint32_t& r3, uint32_t addr) {
    asm volatile("ldmatrix.sync.aligned.m8n8.x4.shared.b16 {%0,%1,%2,%3}, [%4];"
                 : "=r"(r0), "=r"(r1), "=r"(r2), "=r"(r3) : "r"(addr));
}
__device__ __forceinline__ void mma16816h(float* d,
                                          uint32_t a0, uint32_t a1, uint32_t a2, uint32_t a3,
                                          uint32_t b0, uint32_t b1) {
    asm volatile("mma.sync.aligned.m16n8k16.row.col.f32.f16.f16.f32 "
                 "{%0,%1,%2,%3},{%4,%5,%6,%7},{%8,%9},{%0,%1,%2,%3};"
                 : "+f"(d[0]), "+f"(d[1]), "+f"(d[2]), "+f"(d[3])
                 : "r"(a0), "r"(a1), "r"(a2), "r"(a3), "r"(b0), "r"(b1));
}

// fast exp on the FMA pipe (avoids MUFU.EX2 wall at 67M exps).
__device__ __forceinline__ float fast_exp(float x)
{
    float t = x * 1.4426950408889634f;
    t = fmaxf(t, -126.0f);
    float fi = floorf(t);
    float f  = t - fi;
    float p = 1.5403530393381608e-4f;
    p = fmaf(p, f, 1.3333558146428443e-3f);
    p = fmaf(p, f, 9.6181291076284770e-3f);
    p = fmaf(p, f, 5.5504108664821580e-2f);
    p = fmaf(p, f, 2.4022650695910070e-1f);
    p = fmaf(p, f, 6.9314718055994530e-1f);
    p = fmaf(p, f, 1.0f);
    return p * __int_as_float(((int)fi + 127) << 23);
}

// ---------------------------------------------------------------------------
// K1: row L2-normalize (fold 1/sqrt(sigma)), write fp16.
// ---------------------------------------------------------------------------
__global__ void k_normalize(const float* __restrict__ emb)
{
    int row  = blockIdx.x * 4 + (threadIdx.x >> 5);
    int lane = threadIdx.x & 31;
    const float4* src = (const float4*)(emb + (size_t)row * DIM);
    float4 v0 = src[lane];
    float4 v1 = src[lane + 32];
    float s = v0.x*v0.x + v0.y*v0.y + v0.z*v0.z + v0.w*v0.w
            + v1.x*v1.x + v1.y*v1.y + v1.z*v1.z + v1.w*v1.w;
    #pragma unroll
    for (int o = 16; o; o >>= 1) s += __shfl_xor_sync(0xFFFFFFFFu, s, o);
    float nrm = fmaxf(sqrtf(s), 1e-12f);
    float scale = 1.0f / (nrm * 0.316227766016838f);   // 1/(norm*sqrt(sigma))
    __half2* dst = (__half2*)(g_Eh + (size_t)row * DIM);
    dst[lane * 2]            = __floats2half2_rn(v0.x * scale, v0.y * scale);
    dst[lane * 2 + 1]        = __floats2half2_rn(v0.z * scale, v0.w * scale);
    dst[(lane + 32) * 2]     = __floats2half2_rn(v1.x * scale, v1.y * scale);
    dst[(lane + 32) * 2 + 1] = __floats2half2_rn(v1.z * scale, v1.w * scale);
}

// ---------------------------------------------------------------------------
// K2: tiled transpose of V = emb_org -> Vt[c][r] fp16.
// ---------------------------------------------------------------------------
__global__ void k_transpose(const float* __restrict__ emb)
{
    __shared__ float t[32][33];
    int r0 = blockIdx.x * 32;
    int c0 = blockIdx.y * 32;
    int tx = threadIdx.x, ty = threadIdx.y;   // 32 x 8
    #pragma unroll
    for (int i = 0; i < 32; i += 8)
        t[ty + i][tx] = emb[(size_t)(r0 + ty + i) * DIM + c0 + tx];
    __syncthreads();
    #pragma unroll
    for (int i = 0; i < 32; i += 8)
        g_Vt[(size_t)(c0 + ty + i) * NROW + r0 + tx] = __float2half(t[tx][ty + i]);
}

// ---------------------------------------------------------------------------
// Shared MMA: warp tile (MI*16) x (NJB*16), k-chunk 64, permuted smem layout.
// ---------------------------------------------------------------------------
template<int MI, int NJB>
__device__ __forceinline__ void tile_mma_t(float (&acc)[MI][2 * NJB][4], int lane,
                                           int wm, int wn,
                                           uint32_t abase, uint32_t bbase)
{
    #pragma unroll
    for (int kk = 0; kk < 4; kk++) {
        uint32_t a[MI][4];
        #pragma unroll
        for (int mi = 0; mi < MI; mi++) {
            int row = wm + mi * 16 + (lane & 15);
            int k16 = 2 * kk + (lane >> 4);
            ldsm4(a[mi][0], a[mi][1], a[mi][2], a[mi][3],
                  abase + row * 128 + ((k16 ^ (row & 7)) << 4));
        }
        #pragma unroll
        for (int jb = 0; jb < NJB; jb++) {
            uint32_t b[4];
            int row = wn + jb * 16 + (lane & 7) + ((lane >> 4) << 3);
            int k16 = 2 * kk + ((lane >> 3) & 1);
            ldsm4(b[0], b[1], b[2], b[3],
                  bbase + row * 128 + ((k16 ^ (row & 7)) << 4));
            #pragma unroll
            for (int mi = 0; mi < MI; mi++) {
                mma16816h(acc[mi][jb * 2 + 0], a[mi][0], a[mi][1], a[mi][2], a[mi][3], b[0], b[1]);
                mma16816h(acc[mi][jb * 2 + 1], a[mi][0], a[mi][1], a[mi][2], a[mi][3], b[2], b[3]);
            }
        }
    }
}

// ---------------------------------------------------------------------------
// K3: GEMM-S (single fp16 pass, K=256) + fused exp epilogue.
// 128x128 CTA tile, 8 warps (2m x 4n), warp 64x32. 2-stage cp.async.
// Writes U = exp(W-3) fp16 (smem-staged coalesced) + deterministic row-sum
// partials to g_psum[bn_tile][row].
// ---------------------------------------------------------------------------
#define SMSTAGE 32768

__device__ __forceinline__ void s_load(size_t k0, int bm0, int bn0, int tid,
                                       uint32_t stbase)
{
    uint32_t abase = stbase, bbase = stbase + 16384;
    #pragma unroll
    for (int q = 0; q < 4; q++) {
        int v = tid + q * 256;
        int row = v >> 3, k16 = v & 7;
        uint32_t off = row * 128 + ((k16 ^ (row & 7)) << 4);
        cp16(abase + off, g_Eh + (size_t)(bm0 + row) * DIM + k0 + k16 * 8);
        cp16(bbase + off, g_Eh + (size_t)(bn0 + row) * DIM + k0 + k16 * 8);
    }
    cp_commit();
}

__global__ __launch_bounds__(256, 2) void k_gemm_s()
{
    extern __shared__ __align__(1024) char dsm[];
    uint32_t dynb = smem_u32(dsm);
    int tid = threadIdx.x, lane = tid & 31, wid = tid >> 5;
    int wm = (wid >> 2) * 64, wn = (wid & 3) * 32;
    int bm0 = blockIdx.y * 128, bn0 = blockIdx.x * 128;

    float acc[4][4][4];
    #pragma unroll
    for (int i = 0; i < 4; i++)
        #pragma unroll
        for (int j = 0; j < 4; j++)
            #pragma unroll
            for (int q = 0; q < 4; q++) acc[i][j][q] = 0.0f;

    const int NIT = 4;   // 4 chunks of 64 = K 256
    s_load(0, bm0, bn0, tid, dynb);
    for (int it = 0; it < NIT; it++) {
        int s = it & 1;
        if (it + 1 < NIT) {
            s_load((size_t)(it + 1) * 64, bm0, bn0, tid, dynb + ((it + 1) & 1) * SMSTAGE);
            cp_wait<1>();
        } else {
            cp_wait<0>();
        }
        __syncthreads();
        uint32_t base = dynb + s * SMSTAGE;
        tile_mma_t<4, 2>(acc, lane, wm, wn, base, base + 16384);
        __syncthreads();
    }

    // ---- fused epilogue: U = exp(W - 3), row sums, fp16 store ----
    int g = lane >> 2, c2 = (lane & 3) * 2;

    float pa[4], pb[4];
    #pragma unroll
    for (int mi = 0; mi < 4; mi++) { pa[mi] = 0.0f; pb[mi] = 0.0f; }
    #pragma unroll
    for (int mi = 0; mi < 4; mi++)
        #pragma unroll
        for (int nj = 0; nj < 4; nj++) {
            #pragma unroll
            for (int q = 0; q < 4; q++)
                acc[mi][nj][q] = fast_exp(acc[mi][nj][q] - 3.0f);
            pa[mi] += acc[mi][nj][0] + acc[mi][nj][1];
            pb[mi] += acc[mi][nj][2] + acc[mi][nj][3];
        }

    float* ssum = (float*)dsm;   // [4][128]
    #pragma unroll
    for (int mi = 0; mi < 4; mi++) {
        pa[mi] += __shfl_xor_sync(0xFFFFFFFFu, pa[mi], 1);
        pa[mi] += __shfl_xor_sync(0xFFFFFFFFu, pa[mi], 2);
        pb[mi] += __shfl_xor_sync(0xFFFFFFFFu, pb[mi], 1);
        pb[mi] += __shfl_xor_sync(0xFFFFFFFFu, pb[mi], 2);
        if ((lane & 3) == 0) {
            int rl = wm + mi * 16 + g;
            ssum[(wid & 3) * 128 + rl]     = pa[mi];
            ssum[(wid & 3) * 128 + rl + 8] = pb[mi];
        }
    }
    __syncthreads();
    if (tid < 128)
        g_psum[(size_t)blockIdx.x * NROW + bm0 + tid] =
            ssum[tid] + ssum[128 + tid] + ssum[256 + tid] + ssum[384 + tid];
    __syncthreads();

    // smem-staged coalesced fp16 store (row stride 136 halves).
    __half* s16 = (__half*)dsm;
    #pragma unroll
    for (int mi = 0; mi < 4; mi++)
        #pragma unroll
        for (int nj = 0; nj < 4; nj++) {
            int rl = wm + mi * 16 + g, col = wn + nj * 8 + c2;
            *(__half2*)&s16[rl * 136 + col] =
                __floats2half2_rn(acc[mi][nj][0], acc[mi][nj][1]);
            *(__half2*)&s16[(rl + 8) * 136 + col] =
                __floats2half2_rn(acc[mi][nj][2], acc[mi][nj][3]);
        }
    __syncthreads();
    {
        int rr = tid >> 1, hh = tid & 1;
        #pragma unroll
        for (int j = 0; j < 8; j++) {
            uint4 v = *(uint4*)&s16[rr * 136 + hh * 64 + j * 8];
            *(uint4*)&g_U[(size_t)(bm0 + rr) * NROW + bn0 + hh * 64 + j * 8] = v;
        }
    }
}

// ---------------------------------------------------------------------------
// K4: reduce per-tile row sums -> 1/s_i. One warp per row.
// ---------------------------------------------------------------------------
__global__ void k_rowinv()
{
    int row  = blockIdx.x * 8 + (threadIdx.x >> 5);
    int lane = threadIdx.x & 31;
    float s = g_psum[(size_t)(2 * lane) * NROW + row]
            + g_psum[(size_t)(2 * lane + 1) * NROW + row];
    #pragma unroll
    for (int o = 16; o; o >>= 1) s += __shfl_xor_sync(0xFFFFFFFFu, s, o);
    if (lane == 0) g_rinv[row] = 1.0f / s;
}

// ---------------------------------------------------------------------------
// K5: O = (U @ V) * rinv, single fp16 pass.
// CTA tile 64(m) x 256(n) -> grid 128 CTAs, U read exactly once.
// 8 warps (2m x 4n), warp 32x64. Stage = U 8K | V 32K = 40KB, 2 stages.
// ---------------------------------------------------------------------------
#define OSTG 40960

__device__ __forceinline__ void o_load(int it, int bm0, int tid, uint32_t base)
{
    size_t k0 = (size_t)it * 64;
    #pragma unroll
    for (int q = 0; q < 2; q++) {
        int v = tid + q * 256;
        int row = v >> 3, k16 = v & 7;
        uint32_t off = row * 128 + ((k16 ^ (row & 7)) << 4);
        cp16(base + off, g_U + (size_t)(bm0 + row) * NROW + k0 + k16 * 8);
    }
    #pragma unroll
    for (int q = 0; q < 8; q++) {
        int v = tid + q * 256;
        int row = v >> 3, k16 = v & 7;
        uint32_t off = row * 128 + ((k16 ^ (row & 7)) << 4);
        cp16(base + 8192 + off, g_Vt + (size_t)row * NROW + k0 + k16 * 8);
    }
    cp_commit();
}

__global__ __launch_bounds__(256) void k_gemm_o(float* __restrict__ C)
{
    extern __shared__ __align__(1024) char dsm[];
    uint32_t dynb = smem_u32(dsm);
    int tid = threadIdx.x, lane = tid & 31, wid = tid >> 5;
    int wm = (wid >> 2) * 32, wn = (wid & 3) * 64;
    int bm0 = blockIdx.x * 64;

    float acc[2][8][4];
    #pragma unroll
    for (int i = 0; i < 2; i++)
        #pragma unroll
        for (int j = 0; j < 8; j++)
            #pragma unroll
            for (int q = 0; q < 4; q++) acc[i][j][q] = 0.0f;

    const int NIT = 128;   // K = 8192 in chunks of 64
    o_load(0, bm0, tid, dynb);

    #pragma unroll 1
    for (int it = 0; it < NIT; it++) {
        int s = it & 1;
        if (it + 1 < NIT) {
            o_load(it + 1, bm0, tid, dynb + ((it + 1) & 1) * OSTG);
            cp_wait<1>();
        } else {
            cp_wait<0>();
        }
        __syncthreads();
        uint32_t base = dynb + s * OSTG;
        tile_mma_t<2, 4>(acc, lane, wm, wn, base, base + 8192);
        __syncthreads();
    }

    int g = lane >> 2, c2 = (lane & 3) * 2;
    #pragma unroll
    for (int mi = 0; mi < 2; mi++) {
        int ra = bm0 + wm + mi * 16 + g;
        float ia = g_rinv[ra], ib = g_rinv[ra + 8];
        #pragma unroll
        for (int nj = 0; nj < 8; nj++) {
            int col = wn + nj * 8 + c2;
            *(float2*)&C[(size_t)ra * DIM + col] =
                make_float2(acc[mi][nj][0] * ia, acc[mi][nj][1] * ia);
            *(float2*)&C[(size_t)(ra + 8) * DIM + col] =
                make_float2(acc[mi][nj][2] * ib, acc[mi][nj][3] * ib);
        }
    }
}

// ---------------------------------------------------------------------------
extern "C" void kernel_launch(void* const* d_in, const int* in_sizes, int n_in,
                              void* d_out, int out_size)
{
    const float* emb = (const float*)d_in[0];
    float* out = (float*)d_out;

    cudaFuncSetAttribute(k_gemm_s, cudaFuncAttributeMaxDynamicSharedMemorySize, 2 * SMSTAGE);
    cudaFuncSetAttribute(k_gemm_o, cudaFuncAttributeMaxDynamicSharedMemorySize, 2 * OSTG);

    k_normalize<<<NROW / 4, 128>>>(emb);

    dim3 tb(32, 8);
    k_transpose<<<dim3(NROW / 32, DIM / 32), tb>>>(emb);

    k_gemm_s<<<dim3(NROW / 128, NROW / 128), 256, 2 * SMSTAGE>>>();

    k_rowinv<<<NROW / 8, 256>>>();

    k_gemm_o<<<NROW / 64, 256, 2 * OSTG>>>(out);
}

// round 6
// speedup vs baseline: 2.6886x; 1.1613x over previous
#include <cuda_runtime.h>
#include <cuda_fp16.h>
#include <math.h>
#include <stdint.h>

#define NROW 8192
#define DIM  256

// ---------------- scratch (no cudaMalloc allowed) ----------------
static __device__ __half g_U   [(size_t)NROW * NROW];   // 128 MB  exp(W-3) fp16
static __device__ float  g_psum[(size_t)64 * NROW];     // per-colblock row sums
static __device__ float  g_rinv[NROW];                  // 1/rowsum
static __device__ __half g_Eh  [(size_t)NROW * DIM];    // normalized emb / sqrt(sigma)
static __device__ __half g_Vt  [(size_t)DIM * NROW];    // emb_org^T

// ---------------- portable PTX helpers (sm_80+ only) ----------------
__device__ __forceinline__ uint32_t smem_u32(const void* p) {
    return (uint32_t)__cvta_generic_to_shared(p);
}
__device__ __forceinline__ void cp16(uint32_t dst, const void* src) {
    asm volatile("cp.async.cg.shared.global [%0], [%1], 16;"
                 :: "r"(dst), "l"(src) : "memory");
}
__device__ __forceinline__ void cp_commit() {
    asm volatile("cp.async.commit_group;" ::: "memory");
}
template <int N> __device__ __forceinline__ void cp_wait() {
    asm volatile("cp.async.wait_group %0;" :: "n"(N) : "memory");
}
__device__ __forceinline__ void ldsm4(uint32_t& r0, uint32_t& r1,
                                      uint32_t& r2, uint32_t& r3, uint32_t addr) {
    asm volatile("ldmatrix.sync.aligned.m8n8.x4.shared.b16 {%0,%1,%2,%3}, [%4];"
                 : "=r"(r0), "=r"(r1), "=r"(r2), "=r"(r3) : "r"(addr));
}
__device__ __forceinline__ void mma16816h(float* d,
                                          uint32_t a0, uint32_t a1, uint32_t a2, uint32_t a3,
                                          uint32_t b0, uint32_t b1) {
    asm volatile("mma.sync.aligned.m16n8k16.row.col.f32.f16.f16.f32 "
                 "{%0,%1,%2,%3},{%4,%5,%6,%7},{%8,%9},{%0,%1,%2,%3};"
                 : "+f"(d[0]), "+f"(d[1]), "+f"(d[2]), "+f"(d[3])
                 : "r"(a0), "r"(a1), "r"(a2), "r"(a3), "r"(b0), "r"(b1));
}

// fast exp on the FMA pipe (avoids MUFU.EX2 wall at 67M exps).
__device__ __forceinline__ float fast_exp(float x)
{
    float t = x * 1.4426950408889634f;
    t = fmaxf(t, -126.0f);
    float fi = floorf(t);
    float f  = t - fi;
    float p = 1.5403530393381608e-4f;
    p = fmaf(p, f, 1.3333558146428443e-3f);
    p = fmaf(p, f, 9.6181291076284770e-3f);
    p = fmaf(p, f, 5.5504108664821580e-2f);
    p = fmaf(p, f, 2.4022650695910070e-1f);
    p = fmaf(p, f, 6.9314718055994530e-1f);
    p = fmaf(p, f, 1.0f);
    return p * __int_as_float(((int)fi + 127) << 23);
}

// ---------------------------------------------------------------------------
// K1: row L2-normalize (fold 1/sqrt(sigma)), write fp16.
// ---------------------------------------------------------------------------
__global__ void k_normalize(const float* __restrict__ emb)
{
    int row  = blockIdx.x * 4 + (threadIdx.x >> 5);
    int lane = threadIdx.x & 31;
    const float4* src = (const float4*)(emb + (size_t)row * DIM);
    float4 v0 = src[lane];
    float4 v1 = src[lane + 32];
    float s = v0.x*v0.x + v0.y*v0.y + v0.z*v0.z + v0.w*v0.w
            + v1.x*v1.x + v1.y*v1.y + v1.z*v1.z + v1.w*v1.w;
    #pragma unroll
    for (int o = 16; o; o >>= 1) s += __shfl_xor_sync(0xFFFFFFFFu, s, o);
    float nrm = fmaxf(sqrtf(s), 1e-12f);
    float scale = 1.0f / (nrm * 0.316227766016838f);   // 1/(norm*sqrt(sigma))
    __half2* dst = (__half2*)(g_Eh + (size_t)row * DIM);
    dst[lane * 2]            = __floats2half2_rn(v0.x * scale, v0.y * scale);
    dst[lane * 2 + 1]        = __floats2half2_rn(v0.z * scale, v0.w * scale);
    dst[(lane + 32) * 2]     = __floats2half2_rn(v1.x * scale, v1.y * scale);
    dst[(lane + 32) * 2 + 1] = __floats2half2_rn(v1.z * scale, v1.w * scale);
}

// ---------------------------------------------------------------------------
// K2: tiled transpose of V = emb_org -> Vt[c][r] fp16.
// ---------------------------------------------------------------------------
__global__ void k_transpose(const float* __restrict__ emb)
{
    __shared__ float t[32][33];
    int r0 = blockIdx.x * 32;
    int c0 = blockIdx.y * 32;
    int tx = threadIdx.x, ty = threadIdx.y;   // 32 x 8
    #pragma unroll
    for (int i = 0; i < 32; i += 8)
        t[ty + i][tx] = emb[(size_t)(r0 + ty + i) * DIM + c0 + tx];
    __syncthreads();
    #pragma unroll
    for (int i = 0; i < 32; i += 8)
        g_Vt[(size_t)(c0 + ty + i) * NROW + r0 + tx] = __float2half(t[tx][ty + i]);
}

// ---------------------------------------------------------------------------
// Shared MMA: warp tile (MI*16) x (NJB*16), k-chunk 64, permuted smem layout.
// ---------------------------------------------------------------------------
template<int MI, int NJB>
__device__ __forceinline__ void tile_mma_t(float (&acc)[MI][2 * NJB][4], int lane,
                                           int wm, int wn,
                                           uint32_t abase, uint32_t bbase)
{
    #pragma unroll
    for (int kk = 0; kk < 4; kk++) {
        uint32_t a[MI][4];
        #pragma unroll
        for (int mi = 0; mi < MI; mi++) {
            int row = wm + mi * 16 + (lane & 15);
            int k16 = 2 * kk + (lane >> 4);
            ldsm4(a[mi][0], a[mi][1], a[mi][2], a[mi][3],
                  abase + row * 128 + ((k16 ^ (row & 7)) << 4));
        }
        #pragma unroll
        for (int jb = 0; jb < NJB; jb++) {
            uint32_t b[4];
            int row = wn + jb * 16 + (lane & 7) + ((lane >> 4) << 3);
            int k16 = 2 * kk + ((lane >> 3) & 1);
            ldsm4(b[0], b[1], b[2], b[3],
                  bbase + row * 128 + ((k16 ^ (row & 7)) << 4));
            #pragma unroll
            for (int mi = 0; mi < MI; mi++) {
                mma16816h(acc[mi][jb * 2 + 0], a[mi][0], a[mi][1], a[mi][2], a[mi][3], b[0], b[1]);
                mma16816h(acc[mi][jb * 2 + 1], a[mi][0], a[mi][1], a[mi][2], a[mi][3], b[2], b[3]);
            }
        }
    }
}

// ---------------------------------------------------------------------------
// K3: symmetric GEMM-S (triangular grid, 2080 CTAs) + fused exp epilogue.
// Single-shot: full K=256 of A and B tiles loaded up front (128 KB smem),
// one wait, uninterrupted 16 k16-steps of MMA.
// Tile (i,j), i<=j: writes U tile + (if i<j) transposed U tile, row-sum
// partials to psum[j][rows_i] and column-sum partials to psum[i][rows_j].
// ---------------------------------------------------------------------------
__global__ __launch_bounds__(256, 1) void k_gemm_s()
{
    extern __shared__ __align__(1024) char dsm[];
    uint32_t dynb = smem_u32(dsm);
    int tid = threadIdx.x, lane = tid & 31, wid = tid >> 5;
    int wm = (wid >> 2) * 64, wn = (wid & 3) * 32;

    // triangular decode: t -> (i <= j)
    int t = blockIdx.x;
    int j = (int)((sqrtf(8.0f * (float)t + 1.0f) - 1.0f) * 0.5f);
    while ((j + 1) * (j + 2) / 2 <= t) j++;
    while (j * (j + 1) / 2 > t) j--;
    int i = t - j * (j + 1) / 2;
    int bm0 = i * 128, bn0 = j * 128;

    // single-shot load: A chunks at dynb + c*16384, B at dynb + 65536 + c*16384
    #pragma unroll
    for (int c = 0; c < 4; c++) {
        #pragma unroll
        for (int q = 0; q < 4; q++) {
            int v = tid + q * 256;
            int row = v >> 3, k16 = v & 7;
            uint32_t off = row * 128 + ((k16 ^ (row & 7)) << 4);
            cp16(dynb + c * 16384 + off,
                 g_Eh + (size_t)(bm0 + row) * DIM + c * 64 + k16 * 8);
            cp16(dynb + 65536 + c * 16384 + off,
                 g_Eh + (size_t)(bn0 + row) * DIM + c * 64 + k16 * 8);
        }
    }
    cp_commit();

    float acc[4][4][4];
    #pragma unroll
    for (int a = 0; a < 4; a++)
        #pragma unroll
        for (int b = 0; b < 4; b++)
            #pragma unroll
            for (int q = 0; q < 4; q++) acc[a][b][q] = 0.0f;

    cp_wait<0>();
    __syncthreads();
    #pragma unroll
    for (int c = 0; c < 4; c++)
        tile_mma_t<4, 2>(acc, lane, wm, wn,
                         dynb + c * 16384, dynb + 65536 + c * 16384);
    __syncthreads();

    // ---- epilogue: U = exp(W - 3) ----
    int g = lane >> 2, c2 = (lane & 3) * 2;

    float pa[4], pb[4];
    #pragma unroll
    for (int mi = 0; mi < 4; mi++) { pa[mi] = 0.0f; pb[mi] = 0.0f; }
    #pragma unroll
    for (int mi = 0; mi < 4; mi++)
        #pragma unroll
        for (int nj = 0; nj < 4; nj++) {
            #pragma unroll
            for (int q = 0; q < 4; q++)
                acc[mi][nj][q] = fast_exp(acc[mi][nj][q] - 3.0f);
            pa[mi] += acc[mi][nj][0] + acc[mi][nj][1];
            pb[mi] += acc[mi][nj][2] + acc[mi][nj][3];
        }

    // row sums (rows of block i) -> psum[j][bm0 + r]
    float* ssum = (float*)dsm;                    // [4][128]
    float* scol = (float*)(dsm + 2048);           // [2][128]
    #pragma unroll
    for (int mi = 0; mi < 4; mi++) {
        pa[mi] += __shfl_xor_sync(0xFFFFFFFFu, pa[mi], 1);
        pa[mi] += __shfl_xor_sync(0xFFFFFFFFu, pa[mi], 2);
        pb[mi] += __shfl_xor_sync(0xFFFFFFFFu, pb[mi], 1);
        pb[mi] += __shfl_xor_sync(0xFFFFFFFFu, pb[mi], 2);
        if ((lane & 3) == 0) {
            int rl = wm + mi * 16 + g;
            ssum[(wid & 3) * 128 + rl]     = pa[mi];
            ssum[(wid & 3) * 128 + rl + 8] = pb[mi];
        }
    }
    // column sums (rows of block j via symmetry) -> psum[i][bn0 + c]
    if (i != j) {
        float cs0[4], cs1[4];
        #pragma unroll
        for (int nj = 0; nj < 4; nj++) {
            cs0[nj] = 0.0f; cs1[nj] = 0.0f;
            #pragma unroll
            for (int mi = 0; mi < 4; mi++) {
                cs0[nj] += acc[mi][nj][0] + acc[mi][nj][2];
                cs1[nj] += acc[mi][nj][1] + acc[mi][nj][3];
            }
            #pragma unroll
            for (int o = 4; o <= 16; o <<= 1) {
                cs0[nj] += __shfl_xor_sync(0xFFFFFFFFu, cs0[nj], o);
                cs1[nj] += __shfl_xor_sync(0xFFFFFFFFu, cs1[nj], o);
            }
        }
        if (lane < 4) {
            #pragma unroll
            for (int nj = 0; nj < 4; nj++) {
                int col = wn + nj * 8 + lane * 2;
                scol[(wid >> 2) * 128 + col]     = cs0[nj];
                scol[(wid >> 2) * 128 + col + 1] = cs1[nj];
            }
        }
    }
    __syncthreads();
    if (tid < 128) {
        g_psum[(size_t)j * NROW + bm0 + tid] =
            ssum[tid] + ssum[128 + tid] + ssum[256 + tid] + ssum[384 + tid];
        if (i != j)
            g_psum[(size_t)i * NROW + bn0 + tid] = scol[tid] + scol[128 + tid];
    }
    __syncthreads();

    // row-major U tile store (smem-staged, coalesced)
    __half* s16 = (__half*)dsm;
    #pragma unroll
    for (int mi = 0; mi < 4; mi++)
        #pragma unroll
        for (int nj = 0; nj < 4; nj++) {
            int rl = wm + mi * 16 + g, col = wn + nj * 8 + c2;
            *(__half2*)&s16[rl * 136 + col] =
                __floats2half2_rn(acc[mi][nj][0], acc[mi][nj][1]);
            *(__half2*)&s16[(rl + 8) * 136 + col] =
                __floats2half2_rn(acc[mi][nj][2], acc[mi][nj][3]);
        }
    __syncthreads();
    {
        int rr = tid >> 1, hh = tid & 1;
        #pragma unroll
        for (int jb = 0; jb < 8; jb++) {
            uint4 v = *(uint4*)&s16[rr * 136 + hh * 64 + jb * 8];
            *(uint4*)&g_U[(size_t)(bm0 + rr) * NROW + bn0 + hh * 64 + jb * 8] = v;
        }
    }

    // transposed U tile store (only off-diagonal)
    if (i != j) {
        __syncthreads();
        #pragma unroll
        for (int mi = 0; mi < 4; mi++)
            #pragma unroll
            for (int nj = 0; nj < 4; nj++) {
                int rl = wm + mi * 16 + g, col = wn + nj * 8 + c2;
                s16[col * 136 + rl]           = __float2half(acc[mi][nj][0]);
                s16[(col + 1) * 136 + rl]     = __float2half(acc[mi][nj][1]);
                s16[col * 136 + rl + 8]       = __float2half(acc[mi][nj][2]);
                s16[(col + 1) * 136 + rl + 8] = __float2half(acc[mi][nj][3]);
            }
        __syncthreads();
        int rr = tid >> 1, hh = tid & 1;
        #pragma unroll
        for (int jb = 0; jb < 8; jb++) {
            uint4 v = *(uint4*)&s16[rr * 136 + hh * 64 + jb * 8];
            *(uint4*)&g_U[(size_t)(bn0 + rr) * NROW + bm0 + hh * 64 + jb * 8] = v;
        }
    }
}

// ---------------------------------------------------------------------------
// K4: reduce per-colblock row sums -> 1/s_i. One warp per row.
// ---------------------------------------------------------------------------
__global__ void k_rowinv()
{
    int row  = blockIdx.x * 8 + (threadIdx.x >> 5);
    int lane = threadIdx.x & 31;
    float s = g_psum[(size_t)(2 * lane) * NROW + row]
            + g_psum[(size_t)(2 * lane + 1) * NROW + row];
    #pragma unroll
    for (int o = 16; o; o >>= 1) s += __shfl_xor_sync(0xFFFFFFFFu, s, o);
    if (lane == 0) g_rinv[row] = 1.0f / s;
}

// ---------------------------------------------------------------------------
// K5: O = (U @ V) * rinv, single fp16 pass, 3-stage cp.async pipeline.
// CTA tile 64(m) x 256(n) -> 128 CTAs, U read exactly once.
// 8 warps (2m x 4n), warp 32x64. Stage = U 8K | V 32K = 40KB, 3 stages.
// ---------------------------------------------------------------------------
#define OSTG 40960

__device__ __forceinline__ void o_load(int it, int bm0, int tid, uint32_t base)
{
    size_t k0 = (size_t)it * 64;
    #pragma unroll
    for (int q = 0; q < 2; q++) {
        int v = tid + q * 256;
        int row = v >> 3, k16 = v & 7;
        uint32_t off = row * 128 + ((k16 ^ (row & 7)) << 4);
        cp16(base + off, g_U + (size_t)(bm0 + row) * NROW + k0 + k16 * 8);
    }
    #pragma unroll
    for (int q = 0; q < 8; q++) {
        int v = tid + q * 256;
        int row = v >> 3, k16 = v & 7;
        uint32_t off = row * 128 + ((k16 ^ (row & 7)) << 4);
        cp16(base + 8192 + off, g_Vt + (size_t)row * NROW + k0 + k16 * 8);
    }
    cp_commit();
}

__global__ __launch_bounds__(256) void k_gemm_o(float* __restrict__ C)
{
    extern __shared__ __align__(1024) char dsm[];
    uint32_t dynb = smem_u32(dsm);
    int tid = threadIdx.x, lane = tid & 31, wid = tid >> 5;
    int wm = (wid >> 2) * 32, wn = (wid & 3) * 64;
    int bm0 = blockIdx.x * 64;

    float acc[2][8][4];
    #pragma unroll
    for (int a = 0; a < 2; a++)
        #pragma unroll
        for (int b = 0; b < 8; b++)
            #pragma unroll
            for (int q = 0; q < 4; q++) acc[a][b][q] = 0.0f;

    const int NIT = 128;   // K = 8192 in chunks of 64
    o_load(0, bm0, tid, dynb);
    o_load(1, bm0, tid, dynb + OSTG);

    #pragma unroll 1
    for (int it = 0; it < NIT; it++) {
        int s = it % 3;
        if (it + 2 < NIT) {
            o_load(it + 2, bm0, tid, dynb + ((it + 2) % 3) * OSTG);
            cp_wait<2>();
        } else {
            cp_wait<0>();
        }
        __syncthreads();
        uint32_t base = dynb + s * OSTG;
        tile_mma_t<2, 4>(acc, lane, wm, wn, base, base + 8192);
        __syncthreads();
    }

    int g = lane >> 2, c2 = (lane & 3) * 2;
    #pragma unroll
    for (int mi = 0; mi < 2; mi++) {
        int ra = bm0 + wm + mi * 16 + g;
        float ia = g_rinv[ra], ib = g_rinv[ra + 8];
        #pragma unroll
        for (int nj = 0; nj < 8; nj++) {
            int col = wn + nj * 8 + c2;
            *(float2*)&C[(size_t)ra * DIM + col] =
                make_float2(acc[mi][nj][0] * ia, acc[mi][nj][1] * ia);
            *(float2*)&C[(size_t)(ra + 8) * DIM + col] =
                make_float2(acc[mi][nj][2] * ib, acc[mi][nj][3] * ib);
        }
    }
}

// ---------------------------------------------------------------------------
extern "C" void kernel_launch(void* const* d_in, const int* in_sizes, int n_in,
                              void* d_out, int out_size)
{
    const float* emb = (const float*)d_in[0];
    float* out = (float*)d_out;

    cudaFuncSetAttribute(k_gemm_s, cudaFuncAttributeMaxDynamicSharedMemorySize, 131072);
    cudaFuncSetAttribute(k_gemm_o, cudaFuncAttributeMaxDynamicSharedMemorySize, 3 * OSTG);

    k_normalize<<<NROW / 4, 128>>>(emb);

    dim3 tb(32, 8);
    k_transpose<<<dim3(NROW / 32, DIM / 32), tb>>>(emb);

    k_gemm_s<<<2080, 256, 131072>>>();

    k_rowinv<<<NROW / 8, 256>>>();

    k_gemm_o<<<NROW / 64, 256, 3 * OSTG>>>(out);
}

// round 7
// speedup vs baseline: 2.8188x; 1.0484x over previous
#include <cuda_runtime.h>
#include <cuda_fp16.h>
#include <math.h>
#include <stdint.h>

#define NROW 8192
#define DIM  256

// ---------------- scratch (no cudaMalloc allowed) ----------------
static __device__ __half g_U   [(size_t)NROW * NROW];   // 128 MB  exp(W-3) fp16
static __device__ float  g_psum[(size_t)64 * NROW];     // per-colblock row sums
static __device__ float  g_rinv[NROW];                  // 1/rowsum
static __device__ __half g_Eh  [(size_t)NROW * DIM];    // normalized emb / sqrt(sigma)
static __device__ __half g_Vt  [(size_t)DIM * NROW];    // emb_org^T
static __device__ float  g_Opar[2][(size_t)NROW * DIM]; // split-K partial O

// ---------------- portable PTX helpers (sm_80+ only) ----------------
__device__ __forceinline__ uint32_t smem_u32(const void* p) {
    return (uint32_t)__cvta_generic_to_shared(p);
}
__device__ __forceinline__ void cp16(uint32_t dst, const void* src) {
    asm volatile("cp.async.cg.shared.global [%0], [%1], 16;"
                 :: "r"(dst), "l"(src) : "memory");
}
__device__ __forceinline__ void cp_commit() {
    asm volatile("cp.async.commit_group;" ::: "memory");
}
template <int N> __device__ __forceinline__ void cp_wait() {
    asm volatile("cp.async.wait_group %0;" :: "n"(N) : "memory");
}
__device__ __forceinline__ void ldsm4(uint32_t& r0, uint32_t& r1,
                                      uint32_t& r2, uint32_t& r3, uint32_t addr) {
    asm volatile("ldmatrix.sync.aligned.m8n8.x4.shared.b16 {%0,%1,%2,%3}, [%4];"
                 : "=r"(r0), "=r"(r1), "=r"(r2), "=r"(r3) : "r"(addr));
}
__device__ __forceinline__ void mma16816h(float* d,
                                          uint32_t a0, uint32_t a1, uint32_t a2, uint32_t a3,
                                          uint32_t b0, uint32_t b1) {
    asm volatile("mma.sync.aligned.m16n8k16.row.col.f32.f16.f16.f32 "
                 "{%0,%1,%2,%3},{%4,%5,%6,%7},{%8,%9},{%0,%1,%2,%3};"
                 : "+f"(d[0]), "+f"(d[1]), "+f"(d[2]), "+f"(d[3])
                 : "r"(a0), "r"(a1), "r"(a2), "r"(a3), "r"(b0), "r"(b1));
}

// fast exp on the FMA pipe (avoids MUFU.EX2 wall at 67M exps).
__device__ __forceinline__ float fast_exp(float x)
{
    float t = x * 1.4426950408889634f;
    t = fmaxf(t, -126.0f);
    float fi = floorf(t);
    float f  = t - fi;
    float p = 1.5403530393381608e-4f;
    p = fmaf(p, f, 1.3333558146428443e-3f);
    p = fmaf(p, f, 9.6181291076284770e-3f);
    p = fmaf(p, f, 5.5504108664821580e-2f);
    p = fmaf(p, f, 2.4022650695910070e-1f);
    p = fmaf(p, f, 6.9314718055994530e-1f);
    p = fmaf(p, f, 1.0f);
    return p * __int_as_float(((int)fi + 127) << 23);
}

// ---------------------------------------------------------------------------
// K1: row L2-normalize (fold 1/sqrt(sigma)), write fp16.
// ---------------------------------------------------------------------------
__global__ void k_normalize(const float* __restrict__ emb)
{
    int row  = blockIdx.x * 4 + (threadIdx.x >> 5);
    int lane = threadIdx.x & 31;
    const float4* src = (const float4*)(emb + (size_t)row * DIM);
    float4 v0 = src[lane];
    float4 v1 = src[lane + 32];
    float s = v0.x*v0.x + v0.y*v0.y + v0.z*v0.z + v0.w*v0.w
            + v1.x*v1.x + v1.y*v1.y + v1.z*v1.z + v1.w*v1.w;
    #pragma unroll
    for (int o = 16; o; o >>= 1) s += __shfl_xor_sync(0xFFFFFFFFu, s, o);
    float nrm = fmaxf(sqrtf(s), 1e-12f);
    float scale = 1.0f / (nrm * 0.316227766016838f);   // 1/(norm*sqrt(sigma))
    __half2* dst = (__half2*)(g_Eh + (size_t)row * DIM);
    dst[lane * 2]            = __floats2half2_rn(v0.x * scale, v0.y * scale);
    dst[lane * 2 + 1]        = __floats2half2_rn(v0.z * scale, v0.w * scale);
    dst[(lane + 32) * 2]     = __floats2half2_rn(v1.x * scale, v1.y * scale);
    dst[(lane + 32) * 2 + 1] = __floats2half2_rn(v1.z * scale, v1.w * scale);
}

// ---------------------------------------------------------------------------
// K2: tiled transpose of V = emb_org -> Vt[c][r] fp16.
// ---------------------------------------------------------------------------
__global__ void k_transpose(const float* __restrict__ emb)
{
    __shared__ float t[32][33];
    int r0 = blockIdx.x * 32;
    int c0 = blockIdx.y * 32;
    int tx = threadIdx.x, ty = threadIdx.y;   // 32 x 8
    #pragma unroll
    for (int i = 0; i < 32; i += 8)
        t[ty + i][tx] = emb[(size_t)(r0 + ty + i) * DIM + c0 + tx];
    __syncthreads();
    #pragma unroll
    for (int i = 0; i < 32; i += 8)
        g_Vt[(size_t)(c0 + ty + i) * NROW + r0 + tx] = __float2half(t[tx][ty + i]);
}

// ---------------------------------------------------------------------------
// Shared MMA: warp tile (MI*16) x (NJB*16), k-chunk 64, permuted smem layout.
// ---------------------------------------------------------------------------
template<int MI, int NJB>
__device__ __forceinline__ void tile_mma_t(float (&acc)[MI][2 * NJB][4], int lane,
                                           int wm, int wn,
                                           uint32_t abase, uint32_t bbase)
{
    #pragma unroll
    for (int kk = 0; kk < 4; kk++) {
        uint32_t a[MI][4];
        #pragma unroll
        for (int mi = 0; mi < MI; mi++) {
            int row = wm + mi * 16 + (lane & 15);
            int k16 = 2 * kk + (lane >> 4);
            ldsm4(a[mi][0], a[mi][1], a[mi][2], a[mi][3],
                  abase + row * 128 + ((k16 ^ (row & 7)) << 4));
        }
        #pragma unroll
        for (int jb = 0; jb < NJB; jb++) {
            uint32_t b[4];
            int row = wn + jb * 16 + (lane & 7) + ((lane >> 4) << 3);
            int k16 = 2 * kk + ((lane >> 3) & 1);
            ldsm4(b[0], b[1], b[2], b[3],
                  bbase + row * 128 + ((k16 ^ (row & 7)) << 4));
            #pragma unroll
            for (int mi = 0; mi < MI; mi++) {
                mma16816h(acc[mi][jb * 2 + 0], a[mi][0], a[mi][1], a[mi][2], a[mi][3], b[0], b[1]);
                mma16816h(acc[mi][jb * 2 + 1], a[mi][0], a[mi][1], a[mi][2], a[mi][3], b[2], b[3]);
            }
        }
    }
}

// ---------------------------------------------------------------------------
// K3: symmetric GEMM-S (triangular grid, 2080 CTAs) + fused exp epilogue.
// Single-shot: full K=256 of A and B tiles loaded up front (128 KB smem).
// ---------------------------------------------------------------------------
__global__ __launch_bounds__(256, 1) void k_gemm_s()
{
    extern __shared__ __align__(1024) char dsm[];
    uint32_t dynb = smem_u32(dsm);
    int tid = threadIdx.x, lane = tid & 31, wid = tid >> 5;
    int wm = (wid >> 2) * 64, wn = (wid & 3) * 32;

    // triangular decode: t -> (i <= j)
    int t = blockIdx.x;
    int j = (int)((sqrtf(8.0f * (float)t + 1.0f) - 1.0f) * 0.5f);
    while ((j + 1) * (j + 2) / 2 <= t) j++;
    while (j * (j + 1) / 2 > t) j--;
    int i = t - j * (j + 1) / 2;
    int bm0 = i * 128, bn0 = j * 128;

    #pragma unroll
    for (int c = 0; c < 4; c++) {
        #pragma unroll
        for (int q = 0; q < 4; q++) {
            int v = tid + q * 256;
            int row = v >> 3, k16 = v & 7;
            uint32_t off = row * 128 + ((k16 ^ (row & 7)) << 4);
            cp16(dynb + c * 16384 + off,
                 g_Eh + (size_t)(bm0 + row) * DIM + c * 64 + k16 * 8);
            cp16(dynb + 65536 + c * 16384 + off,
                 g_Eh + (size_t)(bn0 + row) * DIM + c * 64 + k16 * 8);
        }
    }
    cp_commit();

    float acc[4][4][4];
    #pragma unroll
    for (int a = 0; a < 4; a++)
        #pragma unroll
        for (int b = 0; b < 4; b++)
            #pragma unroll
            for (int q = 0; q < 4; q++) acc[a][b][q] = 0.0f;

    cp_wait<0>();
    __syncthreads();
    #pragma unroll
    for (int c = 0; c < 4; c++)
        tile_mma_t<4, 2>(acc, lane, wm, wn,
                         dynb + c * 16384, dynb + 65536 + c * 16384);
    __syncthreads();

    // ---- epilogue: U = exp(W - 3) ----
    int g = lane >> 2, c2 = (lane & 3) * 2;

    float pa[4], pb[4];
    #pragma unroll
    for (int mi = 0; mi < 4; mi++) { pa[mi] = 0.0f; pb[mi] = 0.0f; }
    #pragma unroll
    for (int mi = 0; mi < 4; mi++)
        #pragma unroll
        for (int nj = 0; nj < 4; nj++) {
            #pragma unroll
            for (int q = 0; q < 4; q++)
                acc[mi][nj][q] = fast_exp(acc[mi][nj][q] - 3.0f);
            pa[mi] += acc[mi][nj][0] + acc[mi][nj][1];
            pb[mi] += acc[mi][nj][2] + acc[mi][nj][3];
        }

    float* ssum = (float*)dsm;                    // [4][128]
    float* scol = (float*)(dsm + 2048);           // [2][128]
    #pragma unroll
    for (int mi = 0; mi < 4; mi++) {
        pa[mi] += __shfl_xor_sync(0xFFFFFFFFu, pa[mi], 1);
        pa[mi] += __shfl_xor_sync(0xFFFFFFFFu, pa[mi], 2);
        pb[mi] += __shfl_xor_sync(0xFFFFFFFFu, pb[mi], 1);
        pb[mi] += __shfl_xor_sync(0xFFFFFFFFu, pb[mi], 2);
        if ((lane & 3) == 0) {
            int rl = wm + mi * 16 + g;
            ssum[(wid & 3) * 128 + rl]     = pa[mi];
            ssum[(wid & 3) * 128 + rl + 8] = pb[mi];
        }
    }
    if (i != j) {
        float cs0[4], cs1[4];
        #pragma unroll
        for (int nj = 0; nj < 4; nj++) {
            cs0[nj] = 0.0f; cs1[nj] = 0.0f;
            #pragma unroll
            for (int mi = 0; mi < 4; mi++) {
                cs0[nj] += acc[mi][nj][0] + acc[mi][nj][2];
                cs1[nj] += acc[mi][nj][1] + acc[mi][nj][3];
            }
            #pragma unroll
            for (int o = 4; o <= 16; o <<= 1) {
                cs0[nj] += __shfl_xor_sync(0xFFFFFFFFu, cs0[nj], o);
                cs1[nj] += __shfl_xor_sync(0xFFFFFFFFu, cs1[nj], o);
            }
        }
        if (lane < 4) {
            #pragma unroll
            for (int nj = 0; nj < 4; nj++) {
                int col = wn + nj * 8 + lane * 2;
                scol[(wid >> 2) * 128 + col]     = cs0[nj];
                scol[(wid >> 2) * 128 + col + 1] = cs1[nj];
            }
        }
    }
    __syncthreads();
    if (tid < 128) {
        g_psum[(size_t)j * NROW + bm0 + tid] =
            ssum[tid] + ssum[128 + tid] + ssum[256 + tid] + ssum[384 + tid];
        if (i != j)
            g_psum[(size_t)i * NROW + bn0 + tid] = scol[tid] + scol[128 + tid];
    }
    __syncthreads();

    // row-major U tile store (smem-staged, coalesced)
    __half* s16 = (__half*)dsm;
    #pragma unroll
    for (int mi = 0; mi < 4; mi++)
        #pragma unroll
        for (int nj = 0; nj < 4; nj++) {
            int rl = wm + mi * 16 + g, col = wn + nj * 8 + c2;
            *(__half2*)&s16[rl * 136 + col] =
                __floats2half2_rn(acc[mi][nj][0], acc[mi][nj][1]);
            *(__half2*)&s16[(rl + 8) * 136 + col] =
                __floats2half2_rn(acc[mi][nj][2], acc[mi][nj][3]);
        }
    __syncthreads();
    {
        int rr = tid >> 1, hh = tid & 1;
        #pragma unroll
        for (int jb = 0; jb < 8; jb++) {
            uint4 v = *(uint4*)&s16[rr * 136 + hh * 64 + jb * 8];
            *(uint4*)&g_U[(size_t)(bm0 + rr) * NROW + bn0 + hh * 64 + jb * 8] = v;
        }
    }

    // transposed U tile store (only off-diagonal)
    if (i != j) {
        __syncthreads();
        #pragma unroll
        for (int mi = 0; mi < 4; mi++)
            #pragma unroll
            for (int nj = 0; nj < 4; nj++) {
                int rl = wm + mi * 16 + g, col = wn + nj * 8 + c2;
                s16[col * 136 + rl]           = __float2half(acc[mi][nj][0]);
                s16[(col + 1) * 136 + rl]     = __float2half(acc[mi][nj][1]);
                s16[col * 136 + rl + 8]       = __float2half(acc[mi][nj][2]);
                s16[(col + 1) * 136 + rl + 8] = __float2half(acc[mi][nj][3]);
            }
        __syncthreads();
        int rr = tid >> 1, hh = tid & 1;
        #pragma unroll
        for (int jb = 0; jb < 8; jb++) {
            uint4 v = *(uint4*)&s16[rr * 136 + hh * 64 + jb * 8];
            *(uint4*)&g_U[(size_t)(bn0 + rr) * NROW + bm0 + hh * 64 + jb * 8] = v;
        }
    }
}

// ---------------------------------------------------------------------------
// K4: reduce per-colblock row sums -> 1/s_i. One warp per row.
// ---------------------------------------------------------------------------
__global__ void k_rowinv()
{
    int row  = blockIdx.x * 8 + (threadIdx.x >> 5);
    int lane = threadIdx.x & 31;
    float s = g_psum[(size_t)(2 * lane) * NROW + row]
            + g_psum[(size_t)(2 * lane + 1) * NROW + row];
    #pragma unroll
    for (int o = 16; o; o >>= 1) s += __shfl_xor_sync(0xFFFFFFFFu, s, o);
    if (lane == 0) g_rinv[row] = 1.0f / s;
}

// ---------------------------------------------------------------------------
// K5: O-partials = U[.,khalf] @ V[khalf,.], split-K x2.
// Grid (2, 128): 256 CTAs, 2-stage x 40KB -> 2 CTAs/SM (4 warps/SMSP).
// CTA tile 64(m) x 256(n); U read exactly once in aggregate.
// ---------------------------------------------------------------------------
#define OSTG 40960

__device__ __forceinline__ void o_load(size_t k0, int bm0, int tid, uint32_t base)
{
    #pragma unroll
    for (int q = 0; q < 2; q++) {
        int v = tid + q * 256;
        int row = v >> 3, k16 = v & 7;
        uint32_t off = row * 128 + ((k16 ^ (row & 7)) << 4);
        cp16(base + off, g_U + (size_t)(bm0 + row) * NROW + k0 + k16 * 8);
    }
    #pragma unroll
    for (int q = 0; q < 8; q++) {
        int v = tid + q * 256;
        int row = v >> 3, k16 = v & 7;
        uint32_t off = row * 128 + ((k16 ^ (row & 7)) << 4);
        cp16(base + 8192 + off, g_Vt + (size_t)row * NROW + k0 + k16 * 8);
    }
    cp_commit();
}

__global__ __launch_bounds__(256, 2) void k_gemm_o()
{
    extern __shared__ __align__(1024) char dsm[];
    uint32_t dynb = smem_u32(dsm);
    int tid = threadIdx.x, lane = tid & 31, wid = tid >> 5;
    int wm = (wid >> 2) * 32, wn = (wid & 3) * 64;
    int bm0 = blockIdx.y * 64;
    size_t kbase = (size_t)blockIdx.x * 4096;
    float* Opar = g_Opar[blockIdx.x];

    float acc[2][8][4];
    #pragma unroll
    for (int a = 0; a < 2; a++)
        #pragma unroll
        for (int b = 0; b < 8; b++)
            #pragma unroll
            for (int q = 0; q < 4; q++) acc[a][b][q] = 0.0f;

    const int NIT = 64;   // K half = 4096 in chunks of 64
    o_load(kbase, bm0, tid, dynb);

    #pragma unroll 1
    for (int it = 0; it < NIT; it++) {
        int s = it & 1;
        if (it + 1 < NIT) {
            o_load(kbase + (size_t)(it + 1) * 64, bm0, tid,
                   dynb + ((it + 1) & 1) * OSTG);
            cp_wait<1>();
        } else {
            cp_wait<0>();
        }
        __syncthreads();
        uint32_t base = dynb + s * OSTG;
        tile_mma_t<2, 4>(acc, lane, wm, wn, base, base + 8192);
        __syncthreads();
    }

    int g = lane >> 2, c2 = (lane & 3) * 2;
    #pragma unroll
    for (int mi = 0; mi < 2; mi++) {
        int ra = bm0 + wm + mi * 16 + g;
        #pragma unroll
        for (int nj = 0; nj < 8; nj++) {
            int col = wn + nj * 8 + c2;
            *(float2*)&Opar[(size_t)ra * DIM + col] =
                make_float2(acc[mi][nj][0], acc[mi][nj][1]);
            *(float2*)&Opar[(size_t)(ra + 8) * DIM + col] =
                make_float2(acc[mi][nj][2], acc[mi][nj][3]);
        }
    }
}

// ---------------------------------------------------------------------------
// K6: O = (Opar0 + Opar1) * rinv[row].  One float4 per thread.
// ---------------------------------------------------------------------------
__global__ void k_combine(float* __restrict__ C)
{
    size_t idx = (size_t)blockIdx.x * 256 + threadIdx.x;   // float4 index
    int row = (int)(idx >> 6);                             // DIM/4 = 64
    float4 a = ((const float4*)g_Opar[0])[idx];
    float4 b = ((const float4*)g_Opar[1])[idx];
    float r = g_rinv[row];
    ((float4*)C)[idx] = make_float4((a.x + b.x) * r, (a.y + b.y) * r,
                                    (a.z + b.z) * r, (a.w + b.w) * r);
}

// ---------------------------------------------------------------------------
extern "C" void kernel_launch(void* const* d_in, const int* in_sizes, int n_in,
                              void* d_out, int out_size)
{
    const float* emb = (const float*)d_in[0];
    float* out = (float*)d_out;

    cudaFuncSetAttribute(k_gemm_s, cudaFuncAttributeMaxDynamicSharedMemorySize, 131072);
    cudaFuncSetAttribute(k_gemm_o, cudaFuncAttributeMaxDynamicSharedMemorySize, 2 * OSTG);

    k_normalize<<<NROW / 4, 128>>>(emb);

    dim3 tb(32, 8);
    k_transpose<<<dim3(NROW / 32, DIM / 32), tb>>>(emb);

    k_gemm_s<<<2080, 256, 131072>>>();

    k_rowinv<<<NROW / 8, 256>>>();

    k_gemm_o<<<dim3(2, NROW / 64), 256, 2 * OSTG>>>();

    k_combine<<<(NROW * DIM / 4) / 256, 256>>>(out);
}

// round 8
// speedup vs baseline: 3.0903x; 1.0963x over previous
#include <cuda_runtime.h>
#include <cuda_fp16.h>
#include <math.h>
#include <stdint.h>

#define NROW 8192
#define DIM  256

// ---------------- scratch (no cudaMalloc allowed) ----------------
static __device__ __half g_U   [(size_t)NROW * NROW];   // 128 MB  exp(W-3) fp16
static __device__ float  g_psum[(size_t)64 * NROW];     // per-colblock row sums
static __device__ float  g_rinv[NROW];                  // 1/rowsum
static __device__ __half g_Eh  [(size_t)NROW * DIM];    // normalized emb / sqrt(sigma)
static __device__ __half g_Vt  [(size_t)DIM * NROW];    // emb_org^T
static __device__ float  g_Opar[2][(size_t)NROW * DIM]; // split-K partial O

// ---------------- portable PTX helpers (sm_80+ only) ----------------
__device__ __forceinline__ uint32_t smem_u32(const void* p) {
    return (uint32_t)__cvta_generic_to_shared(p);
}
__device__ __forceinline__ void cp16(uint32_t dst, const void* src) {
    asm volatile("cp.async.cg.shared.global [%0], [%1], 16;"
                 :: "r"(dst), "l"(src) : "memory");
}
__device__ __forceinline__ void cp_commit() {
    asm volatile("cp.async.commit_group;" ::: "memory");
}
template <int N> __device__ __forceinline__ void cp_wait() {
    asm volatile("cp.async.wait_group %0;" :: "n"(N) : "memory");
}
__device__ __forceinline__ void ldsm4(uint32_t& r0, uint32_t& r1,
                                      uint32_t& r2, uint32_t& r3, uint32_t addr) {
    asm volatile("ldmatrix.sync.aligned.m8n8.x4.shared.b16 {%0,%1,%2,%3}, [%4];"
                 : "=r"(r0), "=r"(r1), "=r"(r2), "=r"(r3) : "r"(addr));
}
__device__ __forceinline__ void mma16816h(float* d,
                                          uint32_t a0, uint32_t a1, uint32_t a2, uint32_t a3,
                                          uint32_t b0, uint32_t b1) {
    asm volatile("mma.sync.aligned.m16n8k16.row.col.f32.f16.f16.f32 "
                 "{%0,%1,%2,%3},{%4,%5,%6,%7},{%8,%9},{%0,%1,%2,%3};"
                 : "+f"(d[0]), "+f"(d[1]), "+f"(d[2]), "+f"(d[3])
                 : "r"(a0), "r"(a1), "r"(a2), "r"(a3), "r"(b0), "r"(b1));
}

// fast exp on the FMA pipe (avoids MUFU.EX2 wall at 67M exps).
__device__ __forceinline__ float fast_exp(float x)
{
    float t = x * 1.4426950408889634f;
    t = fmaxf(t, -126.0f);
    float fi = floorf(t);
    float f  = t - fi;
    float p = 1.5403530393381608e-4f;
    p = fmaf(p, f, 1.3333558146428443e-3f);
    p = fmaf(p, f, 9.6181291076284770e-3f);
    p = fmaf(p, f, 5.5504108664821580e-2f);
    p = fmaf(p, f, 2.4022650695910070e-1f);
    p = fmaf(p, f, 6.9314718055994530e-1f);
    p = fmaf(p, f, 1.0f);
    return p * __int_as_float(((int)fi + 127) << 23);
}

// ---------------------------------------------------------------------------
// K1: row L2-normalize (fold 1/sqrt(sigma)), write fp16.
// ---------------------------------------------------------------------------
__global__ void k_normalize(const float* __restrict__ emb)
{
    int row  = blockIdx.x * 4 + (threadIdx.x >> 5);
    int lane = threadIdx.x & 31;
    const float4* src = (const float4*)(emb + (size_t)row * DIM);
    float4 v0 = src[lane];
    float4 v1 = src[lane + 32];
    float s = v0.x*v0.x + v0.y*v0.y + v0.z*v0.z + v0.w*v0.w
            + v1.x*v1.x + v1.y*v1.y + v1.z*v1.z + v1.w*v1.w;
    #pragma unroll
    for (int o = 16; o; o >>= 1) s += __shfl_xor_sync(0xFFFFFFFFu, s, o);
    float nrm = fmaxf(sqrtf(s), 1e-12f);
    float scale = 1.0f / (nrm * 0.316227766016838f);   // 1/(norm*sqrt(sigma))
    __half2* dst = (__half2*)(g_Eh + (size_t)row * DIM);
    dst[lane * 2]            = __floats2half2_rn(v0.x * scale, v0.y * scale);
    dst[lane * 2 + 1]        = __floats2half2_rn(v0.z * scale, v0.w * scale);
    dst[(lane + 32) * 2]     = __floats2half2_rn(v1.x * scale, v1.y * scale);
    dst[(lane + 32) * 2 + 1] = __floats2half2_rn(v1.z * scale, v1.w * scale);
}

// ---------------------------------------------------------------------------
// K2: tiled transpose of V = emb_org -> Vt[c][r] fp16.
// ---------------------------------------------------------------------------
__global__ void k_transpose(const float* __restrict__ emb)
{
    __shared__ float t[32][33];
    int r0 = blockIdx.x * 32;
    int c0 = blockIdx.y * 32;
    int tx = threadIdx.x, ty = threadIdx.y;   // 32 x 8
    #pragma unroll
    for (int i = 0; i < 32; i += 8)
        t[ty + i][tx] = emb[(size_t)(r0 + ty + i) * DIM + c0 + tx];
    __syncthreads();
    #pragma unroll
    for (int i = 0; i < 32; i += 8)
        g_Vt[(size_t)(c0 + ty + i) * NROW + r0 + tx] = __float2half(t[tx][ty + i]);
}

// ---------------------------------------------------------------------------
// Shared MMA: warp tile (MI*16) x (NJB*16), k-chunk 64, permuted smem layout.
// ---------------------------------------------------------------------------
template<int MI, int NJB>
__device__ __forceinline__ void tile_mma_t(float (&acc)[MI][2 * NJB][4], int lane,
                                           int wm, int wn,
                                           uint32_t abase, uint32_t bbase)
{
    #pragma unroll
    for (int kk = 0; kk < 4; kk++) {
        uint32_t a[MI][4];
        #pragma unroll
        for (int mi = 0; mi < MI; mi++) {
            int row = wm + mi * 16 + (lane & 15);
            int k16 = 2 * kk + (lane >> 4);
            ldsm4(a[mi][0], a[mi][1], a[mi][2], a[mi][3],
                  abase + row * 128 + ((k16 ^ (row & 7)) << 4));
        }
        #pragma unroll
        for (int jb = 0; jb < NJB; jb++) {
            uint32_t b[4];
            int row = wn + jb * 16 + (lane & 7) + ((lane >> 4) << 3);
            int k16 = 2 * kk + ((lane >> 3) & 1);
            ldsm4(b[0], b[1], b[2], b[3],
                  bbase + row * 128 + ((k16 ^ (row & 7)) << 4));
            #pragma unroll
            for (int mi = 0; mi < MI; mi++) {
                mma16816h(acc[mi][jb * 2 + 0], a[mi][0], a[mi][1], a[mi][2], a[mi][3], b[0], b[1]);
                mma16816h(acc[mi][jb * 2 + 1], a[mi][0], a[mi][1], a[mi][2], a[mi][3], b[2], b[3]);
            }
        }
    }
}

// ---------------------------------------------------------------------------
// K3: symmetric GEMM-S (triangular grid, 2080 CTAs) + fused exp epilogue.
// 2-stage cp.async pipeline over 4 K-chunks (2 x 32 KB smem -> 2 CTAs/SM so
// one CTA's load/epilogue overlaps the other's MMA phase).
// ---------------------------------------------------------------------------
#define SMSTAGE 32768

__device__ __forceinline__ void s_load(size_t k0, int bm0, int bn0, int tid,
                                       uint32_t stbase)
{
    uint32_t abase = stbase, bbase = stbase + 16384;
    #pragma unroll
    for (int q = 0; q < 4; q++) {
        int v = tid + q * 256;
        int row = v >> 3, k16 = v & 7;
        uint32_t off = row * 128 + ((k16 ^ (row & 7)) << 4);
        cp16(abase + off, g_Eh + (size_t)(bm0 + row) * DIM + k0 + k16 * 8);
        cp16(bbase + off, g_Eh + (size_t)(bn0 + row) * DIM + k0 + k16 * 8);
    }
    cp_commit();
}

__global__ __launch_bounds__(256, 2) void k_gemm_s()
{
    extern __shared__ __align__(1024) char dsm[];
    uint32_t dynb = smem_u32(dsm);
    int tid = threadIdx.x, lane = tid & 31, wid = tid >> 5;
    int wm = (wid >> 2) * 64, wn = (wid & 3) * 32;

    // triangular decode: t -> (i <= j)
    int t = blockIdx.x;
    int j = (int)((sqrtf(8.0f * (float)t + 1.0f) - 1.0f) * 0.5f);
    while ((j + 1) * (j + 2) / 2 <= t) j++;
    while (j * (j + 1) / 2 > t) j--;
    int i = t - j * (j + 1) / 2;
    int bm0 = i * 128, bn0 = j * 128;

    float acc[4][4][4];
    #pragma unroll
    for (int a = 0; a < 4; a++)
        #pragma unroll
        for (int b = 0; b < 4; b++)
            #pragma unroll
            for (int q = 0; q < 4; q++) acc[a][b][q] = 0.0f;

    const int NIT = 4;   // 4 chunks of 64 = K 256
    s_load(0, bm0, bn0, tid, dynb);
    for (int it = 0; it < NIT; it++) {
        int s = it & 1;
        if (it + 1 < NIT) {
            s_load((size_t)(it + 1) * 64, bm0, bn0, tid,
                   dynb + ((it + 1) & 1) * SMSTAGE);
            cp_wait<1>();
        } else {
            cp_wait<0>();
        }
        __syncthreads();
        uint32_t base = dynb + s * SMSTAGE;
        tile_mma_t<4, 2>(acc, lane, wm, wn, base, base + 16384);
        __syncthreads();
    }

    // ---- epilogue: U = exp(W - 3) ----
    int g = lane >> 2, c2 = (lane & 3) * 2;

    float pa[4], pb[4];
    #pragma unroll
    for (int mi = 0; mi < 4; mi++) { pa[mi] = 0.0f; pb[mi] = 0.0f; }
    #pragma unroll
    for (int mi = 0; mi < 4; mi++)
        #pragma unroll
        for (int nj = 0; nj < 4; nj++) {
            #pragma unroll
            for (int q = 0; q < 4; q++)
                acc[mi][nj][q] = fast_exp(acc[mi][nj][q] - 3.0f);
            pa[mi] += acc[mi][nj][0] + acc[mi][nj][1];
            pb[mi] += acc[mi][nj][2] + acc[mi][nj][3];
        }

    float* ssum = (float*)dsm;                    // [4][128]
    float* scol = (float*)(dsm + 2048);           // [2][128]
    #pragma unroll
    for (int mi = 0; mi < 4; mi++) {
        pa[mi] += __shfl_xor_sync(0xFFFFFFFFu, pa[mi], 1);
        pa[mi] += __shfl_xor_sync(0xFFFFFFFFu, pa[mi], 2);
        pb[mi] += __shfl_xor_sync(0xFFFFFFFFu, pb[mi], 1);
        pb[mi] += __shfl_xor_sync(0xFFFFFFFFu, pb[mi], 2);
        if ((lane & 3) == 0) {
            int rl = wm + mi * 16 + g;
            ssum[(wid & 3) * 128 + rl]     = pa[mi];
            ssum[(wid & 3) * 128 + rl + 8] = pb[mi];
        }
    }
    if (i != j) {
        float cs0[4], cs1[4];
        #pragma unroll
        for (int nj = 0; nj < 4; nj++) {
            cs0[nj] = 0.0f; cs1[nj] = 0.0f;
            #pragma unroll
            for (int mi = 0; mi < 4; mi++) {
                cs0[nj] += acc[mi][nj][0] + acc[mi][nj][2];
                cs1[nj] += acc[mi][nj][1] + acc[mi][nj][3];
            }
            #pragma unroll
            for (int o = 4; o <= 16; o <<= 1) {
                cs0[nj] += __shfl_xor_sync(0xFFFFFFFFu, cs0[nj], o);
                cs1[nj] += __shfl_xor_sync(0xFFFFFFFFu, cs1[nj], o);
            }
        }
        if (lane < 4) {
            #pragma unroll
            for (int nj = 0; nj < 4; nj++) {
                int col = wn + nj * 8 + lane * 2;
                scol[(wid >> 2) * 128 + col]     = cs0[nj];
                scol[(wid >> 2) * 128 + col + 1] = cs1[nj];
            }
        }
    }
    __syncthreads();
    if (tid < 128) {
        g_psum[(size_t)j * NROW + bm0 + tid] =
            ssum[tid] + ssum[128 + tid] + ssum[256 + tid] + ssum[384 + tid];
        if (i != j)
            g_psum[(size_t)i * NROW + bn0 + tid] = scol[tid] + scol[128 + tid];
    }
    __syncthreads();

    // row-major U tile store (smem-staged, coalesced)
    __half* s16 = (__half*)dsm;
    #pragma unroll
    for (int mi = 0; mi < 4; mi++)
        #pragma unroll
        for (int nj = 0; nj < 4; nj++) {
            int rl = wm + mi * 16 + g, col = wn + nj * 8 + c2;
            *(__half2*)&s16[rl * 136 + col] =
                __floats2half2_rn(acc[mi][nj][0], acc[mi][nj][1]);
            *(__half2*)&s16[(rl + 8) * 136 + col] =
                __floats2half2_rn(acc[mi][nj][2], acc[mi][nj][3]);
        }
    __syncthreads();
    {
        int rr = tid >> 1, hh = tid & 1;
        #pragma unroll
        for (int jb = 0; jb < 8; jb++) {
            uint4 v = *(uint4*)&s16[rr * 136 + hh * 64 + jb * 8];
            *(uint4*)&g_U[(size_t)(bm0 + rr) * NROW + bn0 + hh * 64 + jb * 8] = v;
        }
    }

    // transposed U tile store (only off-diagonal)
    if (i != j) {
        __syncthreads();
        #pragma unroll
        for (int mi = 0; mi < 4; mi++)
            #pragma unroll
            for (int nj = 0; nj < 4; nj++) {
                int rl = wm + mi * 16 + g, col = wn + nj * 8 + c2;
                s16[col * 136 + rl]           = __float2half(acc[mi][nj][0]);
                s16[(col + 1) * 136 + rl]     = __float2half(acc[mi][nj][1]);
                s16[col * 136 + rl + 8]       = __float2half(acc[mi][nj][2]);
                s16[(col + 1) * 136 + rl + 8] = __float2half(acc[mi][nj][3]);
            }
        __syncthreads();
        int rr = tid >> 1, hh = tid & 1;
        #pragma unroll
        for (int jb = 0; jb < 8; jb++) {
            uint4 v = *(uint4*)&s16[rr * 136 + hh * 64 + jb * 8];
            *(uint4*)&g_U[(size_t)(bn0 + rr) * NROW + bm0 + hh * 64 + jb * 8] = v;
        }
    }
}

// ---------------------------------------------------------------------------
// K4: reduce per-colblock row sums -> 1/s_i. One warp per row.
// ---------------------------------------------------------------------------
__global__ void k_rowinv()
{
    int row  = blockIdx.x * 8 + (threadIdx.x >> 5);
    int lane = threadIdx.x & 31;
    float s = g_psum[(size_t)(2 * lane) * NROW + row]
            + g_psum[(size_t)(2 * lane + 1) * NROW + row];
    #pragma unroll
    for (int o = 16; o; o >>= 1) s += __shfl_xor_sync(0xFFFFFFFFu, s, o);
    if (lane == 0) g_rinv[row] = 1.0f / s;
}

// ---------------------------------------------------------------------------
// K5: O-partials = U[.,khalf] @ V[khalf,.], split-K x2.
// Grid (2, 128): 256 CTAs, 2-stage x 40KB -> 2 CTAs/SM (4 warps/SMSP).
// CTA tile 64(m) x 256(n); U read exactly once in aggregate.
// ---------------------------------------------------------------------------
#define OSTG 40960

__device__ __forceinline__ void o_load(size_t k0, int bm0, int tid, uint32_t base)
{
    #pragma unroll
    for (int q = 0; q < 2; q++) {
        int v = tid + q * 256;
        int row = v >> 3, k16 = v & 7;
        uint32_t off = row * 128 + ((k16 ^ (row & 7)) << 4);
        cp16(base + off, g_U + (size_t)(bm0 + row) * NROW + k0 + k16 * 8);
    }
    #pragma unroll
    for (int q = 0; q < 8; q++) {
        int v = tid + q * 256;
        int row = v >> 3, k16 = v & 7;
        uint32_t off = row * 128 + ((k16 ^ (row & 7)) << 4);
        cp16(base + 8192 + off, g_Vt + (size_t)row * NROW + k0 + k16 * 8);
    }
    cp_commit();
}

__global__ __launch_bounds__(256, 2) void k_gemm_o()
{
    extern __shared__ __align__(1024) char dsm[];
    uint32_t dynb = smem_u32(dsm);
    int tid = threadIdx.x, lane = tid & 31, wid = tid >> 5;
    int wm = (wid >> 2) * 32, wn = (wid & 3) * 64;
    int bm0 = blockIdx.y * 64;
    size_t kbase = (size_t)blockIdx.x * 4096;
    float* Opar = g_Opar[blockIdx.x];

    float acc[2][8][4];
    #pragma unroll
    for (int a = 0; a < 2; a++)
        #pragma unroll
        for (int b = 0; b < 8; b++)
            #pragma unroll
            for (int q = 0; q < 4; q++) acc[a][b][q] = 0.0f;

    const int NIT = 64;   // K half = 4096 in chunks of 64
    o_load(kbase, bm0, tid, dynb);

    #pragma unroll 1
    for (int it = 0; it < NIT; it++) {
        int s = it & 1;
        if (it + 1 < NIT) {
            o_load(kbase + (size_t)(it + 1) * 64, bm0, tid,
                   dynb + ((it + 1) & 1) * OSTG);
            cp_wait<1>();
        } else {
            cp_wait<0>();
        }
        __syncthreads();
        uint32_t base = dynb + s * OSTG;
        tile_mma_t<2, 4>(acc, lane, wm, wn, base, base + 8192);
        __syncthreads();
    }

    int g = lane >> 2, c2 = (lane & 3) * 2;
    #pragma unroll
    for (int mi = 0; mi < 2; mi++) {
        int ra = bm0 + wm + mi * 16 + g;
        #pragma unroll
        for (int nj = 0; nj < 8; nj++) {
            int col = wn + nj * 8 + c2;
            *(float2*)&Opar[(size_t)ra * DIM + col] =
                make_float2(acc[mi][nj][0], acc[mi][nj][1]);
            *(float2*)&Opar[(size_t)(ra + 8) * DIM + col] =
                make_float2(acc[mi][nj][2], acc[mi][nj][3]);
        }
    }
}

// ---------------------------------------------------------------------------
// K6: O = (Opar0 + Opar1) * rinv[row].  One float4 per thread.
// ---------------------------------------------------------------------------
__global__ void k_combine(float* __restrict__ C)
{
    size_t idx = (size_t)blockIdx.x * 256 + threadIdx.x;   // float4 index
    int row = (int)(idx >> 6);                             // DIM/4 = 64
    float4 a = ((const float4*)g_Opar[0])[idx];
    float4 b = ((const float4*)g_Opar[1])[idx];
    float r = g_rinv[row];
    ((float4*)C)[idx] = make_float4((a.x + b.x) * r, (a.y + b.y) * r,
                                    (a.z + b.z) * r, (a.w + b.w) * r);
}

// ---------------------------------------------------------------------------
extern "C" void kernel_launch(void* const* d_in, const int* in_sizes, int n_in,
                              void* d_out, int out_size)
{
    const float* emb = (const float*)d_in[0];
    float* out = (float*)d_out;

    cudaFuncSetAttribute(k_gemm_s, cudaFuncAttributeMaxDynamicSharedMemorySize, 2 * SMSTAGE);
    cudaFuncSetAttribute(k_gemm_o, cudaFuncAttributeMaxDynamicSharedMemorySize, 2 * OSTG);

    k_normalize<<<NROW / 4, 128>>>(emb);

    dim3 tb(32, 8);
    k_transpose<<<dim3(NROW / 32, DIM / 32), tb>>>(emb);

    k_gemm_s<<<2080, 256, 2 * SMSTAGE>>>();

    k_rowinv<<<NROW / 8, 256>>>();

    k_gemm_o<<<dim3(2, NROW / 64), 256, 2 * OSTG>>>();

    k_combine<<<(NROW * DIM / 4) / 256, 256>>>(out);
}

// round 9
// speedup vs baseline: 3.3001x; 1.0679x over previous
#include <cuda_runtime.h>
#include <cuda_fp16.h>
#include <math.h>
#include <stdint.h>

#define NROW 8192
#define DIM  256

// ---------------- scratch (no cudaMalloc allowed) ----------------
static __device__ __half g_U   [(size_t)NROW * NROW];   // upper-tri tiles of exp(W-3)
static __device__ float  g_psum[(size_t)64 * NROW];     // per-colblock row sums
static __device__ __half g_Eh  [(size_t)NROW * DIM];    // normalized emb / sqrt(sigma)
static __device__ __half g_Vt  [(size_t)DIM * NROW];    // emb_org^T
static __device__ float  g_Opar[2][(size_t)NROW * DIM]; // split-K partial O

// ---------------- portable PTX helpers (sm_80+ only) ----------------
__device__ __forceinline__ uint32_t smem_u32(const void* p) {
    return (uint32_t)__cvta_generic_to_shared(p);
}
__device__ __forceinline__ void cp16(uint32_t dst, const void* src) {
    asm volatile("cp.async.cg.shared.global [%0], [%1], 16;"
                 :: "r"(dst), "l"(src) : "memory");
}
__device__ __forceinline__ void cp_commit() {
    asm volatile("cp.async.commit_group;" ::: "memory");
}
template <int N> __device__ __forceinline__ void cp_wait() {
    asm volatile("cp.async.wait_group %0;" :: "n"(N) : "memory");
}
__device__ __forceinline__ void ldsm4(uint32_t& r0, uint32_t& r1,
                                      uint32_t& r2, uint32_t& r3, uint32_t addr) {
    asm volatile("ldmatrix.sync.aligned.m8n8.x4.shared.b16 {%0,%1,%2,%3}, [%4];"
                 : "=r"(r0), "=r"(r1), "=r"(r2), "=r"(r3) : "r"(addr));
}
__device__ __forceinline__ void ldsm4t(uint32_t& r0, uint32_t& r1,
                                       uint32_t& r2, uint32_t& r3, uint32_t addr) {
    asm volatile("ldmatrix.sync.aligned.m8n8.x4.trans.shared.b16 {%0,%1,%2,%3}, [%4];"
                 : "=r"(r0), "=r"(r1), "=r"(r2), "=r"(r3) : "r"(addr));
}
__device__ __forceinline__ void mma16816h(float* d,
                                          uint32_t a0, uint32_t a1, uint32_t a2, uint32_t a3,
                                          uint32_t b0, uint32_t b1) {
    asm volatile("mma.sync.aligned.m16n8k16.row.col.f32.f16.f16.f32 "
                 "{%0,%1,%2,%3},{%4,%5,%6,%7},{%8,%9},{%0,%1,%2,%3};"
                 : "+f"(d[0]), "+f"(d[1]), "+f"(d[2]), "+f"(d[3])
                 : "r"(a0), "r"(a1), "r"(a2), "r"(a3), "r"(b0), "r"(b1));
}

// fast exp on the FMA pipe (avoids MUFU.EX2 wall at 67M exps).
__device__ __forceinline__ float fast_exp(float x)
{
    float t = x * 1.4426950408889634f;
    t = fmaxf(t, -126.0f);
    float fi = floorf(t);
    float f  = t - fi;
    float p = 1.5403530393381608e-4f;
    p = fmaf(p, f, 1.3333558146428443e-3f);
    p = fmaf(p, f, 9.6181291076284770e-3f);
    p = fmaf(p, f, 5.5504108664821580e-2f);
    p = fmaf(p, f, 2.4022650695910070e-1f);
    p = fmaf(p, f, 6.9314718055994530e-1f);
    p = fmaf(p, f, 1.0f);
    return p * __int_as_float(((int)fi + 127) << 23);
}

// ---------------------------------------------------------------------------
// K1: row L2-normalize (fold 1/sqrt(sigma)), write fp16.
// ---------------------------------------------------------------------------
__global__ void k_normalize(const float* __restrict__ emb)
{
    int row  = blockIdx.x * 4 + (threadIdx.x >> 5);
    int lane = threadIdx.x & 31;
    const float4* src = (const float4*)(emb + (size_t)row * DIM);
    float4 v0 = src[lane];
    float4 v1 = src[lane + 32];
    float s = v0.x*v0.x + v0.y*v0.y + v0.z*v0.z + v0.w*v0.w
            + v1.x*v1.x + v1.y*v1.y + v1.z*v1.z + v1.w*v1.w;
    #pragma unroll
    for (int o = 16; o; o >>= 1) s += __shfl_xor_sync(0xFFFFFFFFu, s, o);
    float nrm = fmaxf(sqrtf(s), 1e-12f);
    float scale = 1.0f / (nrm * 0.316227766016838f);   // 1/(norm*sqrt(sigma))
    __half2* dst = (__half2*)(g_Eh + (size_t)row * DIM);
    dst[lane * 2]            = __floats2half2_rn(v0.x * scale, v0.y * scale);
    dst[lane * 2 + 1]        = __floats2half2_rn(v0.z * scale, v0.w * scale);
    dst[(lane + 32) * 2]     = __floats2half2_rn(v1.x * scale, v1.y * scale);
    dst[(lane + 32) * 2 + 1] = __floats2half2_rn(v1.z * scale, v1.w * scale);
}

// ---------------------------------------------------------------------------
// K2: tiled transpose of V = emb_org -> Vt[c][r] fp16.
// ---------------------------------------------------------------------------
__global__ void k_transpose(const float* __restrict__ emb)
{
    __shared__ float t[32][33];
    int r0 = blockIdx.x * 32;
    int c0 = blockIdx.y * 32;
    int tx = threadIdx.x, ty = threadIdx.y;   // 32 x 8
    #pragma unroll
    for (int i = 0; i < 32; i += 8)
        t[ty + i][tx] = emb[(size_t)(r0 + ty + i) * DIM + c0 + tx];
    __syncthreads();
    #pragma unroll
    for (int i = 0; i < 32; i += 8)
        g_Vt[(size_t)(c0 + ty + i) * NROW + r0 + tx] = __float2half(t[tx][ty + i]);
}

// ---------------------------------------------------------------------------
// Shared MMA (A row-major in smem): warp tile (MI*16) x (NJB*16), k-chunk 64.
// ---------------------------------------------------------------------------
template<int MI, int NJB>
__device__ __forceinline__ void tile_mma_t(float (&acc)[MI][2 * NJB][4], int lane,
                                           int wm, int wn,
                                           uint32_t abase, uint32_t bbase)
{
    #pragma unroll
    for (int kk = 0; kk < 4; kk++) {
        uint32_t a[MI][4];
        #pragma unroll
        for (int mi = 0; mi < MI; mi++) {
            int row = wm + mi * 16 + (lane & 15);
            int k16 = 2 * kk + (lane >> 4);
            ldsm4(a[mi][0], a[mi][1], a[mi][2], a[mi][3],
                  abase + row * 128 + ((k16 ^ (row & 7)) << 4));
        }
        #pragma unroll
        for (int jb = 0; jb < NJB; jb++) {
            uint32_t b[4];
            int row = wn + jb * 16 + (lane & 7) + ((lane >> 4) << 3);
            int k16 = 2 * kk + ((lane >> 3) & 1);
            ldsm4(b[0], b[1], b[2], b[3],
                  bbase + row * 128 + ((k16 ^ (row & 7)) << 4));
            #pragma unroll
            for (int mi = 0; mi < MI; mi++) {
                mma16816h(acc[mi][jb * 2 + 0], a[mi][0], a[mi][1], a[mi][2], a[mi][3], b[0], b[1]);
                mma16816h(acc[mi][jb * 2 + 1], a[mi][0], a[mi][1], a[mi][2], a[mi][3], b[2], b[3]);
            }
        }
    }
}

// ---------------------------------------------------------------------------
// GEMM-O MMA with A either row-major or TRANSPOSED in smem (tile stored as
// [k][m]; A fragments built via ldmatrix.x4.trans):
//  matrix q of the 16x16 A-fragment = S[rows c..c+7][cols r..r+8]^T, so lane
//  addressing: srow = kk*16 + 8*(lane>>4) + (lane&7),
//              colgroup = (m_off>>3) + ((lane>>3)&1).
// ---------------------------------------------------------------------------
template<int MI, int NJB>
__device__ __forceinline__ void tile_mma_o(float (&acc)[MI][2 * NJB][4], int lane,
                                           int wm, int wn,
                                           uint32_t abase, uint32_t bbase, int trans)
{
    #pragma unroll
    for (int kk = 0; kk < 4; kk++) {
        uint32_t a[MI][4];
        if (!trans) {
            #pragma unroll
            for (int mi = 0; mi < MI; mi++) {
                int row = wm + mi * 16 + (lane & 15);
                int k16 = 2 * kk + (lane >> 4);
                ldsm4(a[mi][0], a[mi][1], a[mi][2], a[mi][3],
                      abase + row * 128 + ((k16 ^ (row & 7)) << 4));
            }
        } else {
            #pragma unroll
            for (int mi = 0; mi < MI; mi++) {
                int srow = kk * 16 + ((lane >> 4) << 3) + (lane & 7);
                int cg = ((wm + mi * 16) >> 3) + ((lane >> 3) & 1);
                ldsm4t(a[mi][0], a[mi][1], a[mi][2], a[mi][3],
                       abase + srow * 128 + ((cg ^ (srow & 7)) << 4));
            }
        }
        #pragma unroll
        for (int jb = 0; jb < NJB; jb++) {
            uint32_t b[4];
            int row = wn + jb * 16 + (lane & 7) + ((lane >> 4) << 3);
            int k16 = 2 * kk + ((lane >> 3) & 1);
            ldsm4(b[0], b[1], b[2], b[3],
                  bbase + row * 128 + ((k16 ^ (row & 7)) << 4));
            #pragma unroll
            for (int mi = 0; mi < MI; mi++) {
                mma16816h(acc[mi][jb * 2 + 0], a[mi][0], a[mi][1], a[mi][2], a[mi][3], b[0], b[1]);
                mma16816h(acc[mi][jb * 2 + 1], a[mi][0], a[mi][1], a[mi][2], a[mi][3], b[2], b[3]);
            }
        }
    }
}

// ---------------------------------------------------------------------------
// K3: symmetric GEMM-S (triangular grid, 2080 CTAs) + fused exp epilogue.
// 2-stage cp.async pipeline, 2 CTAs/SM. Stores ONLY the upper-tri U tile
// (row-major); GEMM-O reads the mirror via ldmatrix.trans.
// ---------------------------------------------------------------------------
#define SMSTAGE 32768

__device__ __forceinline__ void s_load(size_t k0, int bm0, int bn0, int tid,
                                       uint32_t stbase)
{
    uint32_t abase = stbase, bbase = stbase + 16384;
    #pragma unroll
    for (int q = 0; q < 4; q++) {
        int v = tid + q * 256;
        int row = v >> 3, k16 = v & 7;
        uint32_t off = row * 128 + ((k16 ^ (row & 7)) << 4);
        cp16(abase + off, g_Eh + (size_t)(bm0 + row) * DIM + k0 + k16 * 8);
        cp16(bbase + off, g_Eh + (size_t)(bn0 + row) * DIM + k0 + k16 * 8);
    }
    cp_commit();
}

__global__ __launch_bounds__(256, 2) void k_gemm_s()
{
    extern __shared__ __align__(1024) char dsm[];
    uint32_t dynb = smem_u32(dsm);
    int tid = threadIdx.x, lane = tid & 31, wid = tid >> 5;
    int wm = (wid >> 2) * 64, wn = (wid & 3) * 32;

    // triangular decode: t -> (i <= j)
    int t = blockIdx.x;
    int j = (int)((sqrtf(8.0f * (float)t + 1.0f) - 1.0f) * 0.5f);
    while ((j + 1) * (j + 2) / 2 <= t) j++;
    while (j * (j + 1) / 2 > t) j--;
    int i = t - j * (j + 1) / 2;
    int bm0 = i * 128, bn0 = j * 128;

    float acc[4][4][4];
    #pragma unroll
    for (int a = 0; a < 4; a++)
        #pragma unroll
        for (int b = 0; b < 4; b++)
            #pragma unroll
            for (int q = 0; q < 4; q++) acc[a][b][q] = 0.0f;

    const int NIT = 4;   // 4 chunks of 64 = K 256
    s_load(0, bm0, bn0, tid, dynb);
    for (int it = 0; it < NIT; it++) {
        int s = it & 1;
        if (it + 1 < NIT) {
            s_load((size_t)(it + 1) * 64, bm0, bn0, tid,
                   dynb + ((it + 1) & 1) * SMSTAGE);
            cp_wait<1>();
        } else {
            cp_wait<0>();
        }
        __syncthreads();
        uint32_t base = dynb + s * SMSTAGE;
        tile_mma_t<4, 2>(acc, lane, wm, wn, base, base + 16384);
        __syncthreads();
    }

    // ---- epilogue: U = exp(W - 3) ----
    int g = lane >> 2, c2 = (lane & 3) * 2;

    float pa[4], pb[4];
    #pragma unroll
    for (int mi = 0; mi < 4; mi++) { pa[mi] = 0.0f; pb[mi] = 0.0f; }
    #pragma unroll
    for (int mi = 0; mi < 4; mi++)
        #pragma unroll
        for (int nj = 0; nj < 4; nj++) {
            #pragma unroll
            for (int q = 0; q < 4; q++)
                acc[mi][nj][q] = fast_exp(acc[mi][nj][q] - 3.0f);
            pa[mi] += acc[mi][nj][0] + acc[mi][nj][1];
            pb[mi] += acc[mi][nj][2] + acc[mi][nj][3];
        }

    float* ssum = (float*)dsm;                    // [4][128]
    float* scol = (float*)(dsm + 2048);           // [2][128]
    #pragma unroll
    for (int mi = 0; mi < 4; mi++) {
        pa[mi] += __shfl_xor_sync(0xFFFFFFFFu, pa[mi], 1);
        pa[mi] += __shfl_xor_sync(0xFFFFFFFFu, pa[mi], 2);
        pb[mi] += __shfl_xor_sync(0xFFFFFFFFu, pb[mi], 1);
        pb[mi] += __shfl_xor_sync(0xFFFFFFFFu, pb[mi], 2);
        if ((lane & 3) == 0) {
            int rl = wm + mi * 16 + g;
            ssum[(wid & 3) * 128 + rl]     = pa[mi];
            ssum[(wid & 3) * 128 + rl + 8] = pb[mi];
        }
    }
    if (i != j) {
        float cs0[4], cs1[4];
        #pragma unroll
        for (int nj = 0; nj < 4; nj++) {
            cs0[nj] = 0.0f; cs1[nj] = 0.0f;
            #pragma unroll
            for (int mi = 0; mi < 4; mi++) {
                cs0[nj] += acc[mi][nj][0] + acc[mi][nj][2];
                cs1[nj] += acc[mi][nj][1] + acc[mi][nj][3];
            }
            #pragma unroll
            for (int o = 4; o <= 16; o <<= 1) {
                cs0[nj] += __shfl_xor_sync(0xFFFFFFFFu, cs0[nj], o);
                cs1[nj] += __shfl_xor_sync(0xFFFFFFFFu, cs1[nj], o);
            }
        }
        if (lane < 4) {
            #pragma unroll
            for (int nj = 0; nj < 4; nj++) {
                int col = wn + nj * 8 + lane * 2;
                scol[(wid >> 2) * 128 + col]     = cs0[nj];
                scol[(wid >> 2) * 128 + col + 1] = cs1[nj];
            }
        }
    }
    __syncthreads();
    if (tid < 128) {
        g_psum[(size_t)j * NROW + bm0 + tid] =
            ssum[tid] + ssum[128 + tid] + ssum[256 + tid] + ssum[384 + tid];
        if (i != j)
            g_psum[(size_t)i * NROW + bn0 + tid] = scol[tid] + scol[128 + tid];
    }
    __syncthreads();

    // row-major U tile store (smem-staged, coalesced) — upper triangle only.
    __half* s16 = (__half*)dsm;
    #pragma unroll
    for (int mi = 0; mi < 4; mi++)
        #pragma unroll
        for (int nj = 0; nj < 4; nj++) {
            int rl = wm + mi * 16 + g, col = wn + nj * 8 + c2;
            *(__half2*)&s16[rl * 136 + col] =
                __floats2half2_rn(acc[mi][nj][0], acc[mi][nj][1]);
            *(__half2*)&s16[(rl + 8) * 136 + col] =
                __floats2half2_rn(acc[mi][nj][2], acc[mi][nj][3]);
        }
    __syncthreads();
    {
        int rr = tid >> 1, hh = tid & 1;
        #pragma unroll
        for (int jb = 0; jb < 8; jb++) {
            uint4 v = *(uint4*)&s16[rr * 136 + hh * 64 + jb * 8];
            *(uint4*)&g_U[(size_t)(bm0 + rr) * NROW + bn0 + hh * 64 + jb * 8] = v;
        }
    }
}

// ---------------------------------------------------------------------------
// K5: O-partials = U[.,khalf] @ V[khalf,.], split-K x2.
// Grid (2, 128): 256 CTAs, 2-stage x 40KB -> 2 CTAs/SM.
// For k-blocks below the diagonal the U tile is read from its mirrored
// location (U symmetric) and consumed via ldmatrix.trans.
// ---------------------------------------------------------------------------
#define OSTG 40960

__device__ __forceinline__ void o_load(size_t k0, int bm0, int tid, uint32_t base,
                                       int trans)
{
    #pragma unroll
    for (int q = 0; q < 2; q++) {
        int v = tid + q * 256;
        int row = v >> 3, k16 = v & 7;
        uint32_t off = row * 128 + ((k16 ^ (row & 7)) << 4);
        const __half* src = trans
            ? g_U + (k0 + row) * NROW + bm0 + k16 * 8      // [k][m] tile
            : g_U + (size_t)(bm0 + row) * NROW + k0 + k16 * 8;  // [m][k] tile
        cp16(base + off, src);
    }
    #pragma unroll
    for (int q = 0; q < 8; q++) {
        int v = tid + q * 256;
        int row = v >> 3, k16 = v & 7;
        uint32_t off = row * 128 + ((k16 ^ (row & 7)) << 4);
        cp16(base + 8192 + off, g_Vt + (size_t)row * NROW + k0 + k16 * 8);
    }
    cp_commit();
}

__global__ __launch_bounds__(256, 2) void k_gemm_o()
{
    extern __shared__ __align__(1024) char dsm[];
    uint32_t dynb = smem_u32(dsm);
    int tid = threadIdx.x, lane = tid & 31, wid = tid >> 5;
    int wm = (wid >> 2) * 32, wn = (wid & 3) * 64;
    int bm0 = blockIdx.y * 64;
    size_t kbase = (size_t)blockIdx.x * 4096;
    float* Opar = g_Opar[blockIdx.x];
    int ib = bm0 >> 7;

    float acc[2][8][4];
    #pragma unroll
    for (int a = 0; a < 2; a++)
        #pragma unroll
        for (int b = 0; b < 8; b++)
            #pragma unroll
            for (int q = 0; q < 4; q++) acc[a][b][q] = 0.0f;

    const int NIT = 64;   // K half = 4096 in chunks of 64
    {
        int tr0 = ((int)(kbase >> 7)) < ib;
        o_load(kbase, bm0, tid, dynb, tr0);
    }

    #pragma unroll 1
    for (int it = 0; it < NIT; it++) {
        int s = it & 1;
        size_t k0 = kbase + (size_t)it * 64;
        int trans = ((int)(k0 >> 7)) < ib;
        if (it + 1 < NIT) {
            size_t kn = kbase + (size_t)(it + 1) * 64;
            o_load(kn, bm0, tid, dynb + ((it + 1) & 1) * OSTG,
                   ((int)(kn >> 7)) < ib);
            cp_wait<1>();
        } else {
            cp_wait<0>();
        }
        __syncthreads();
        uint32_t base = dynb + s * OSTG;
        tile_mma_o<2, 4>(acc, lane, wm, wn, base, base + 8192, trans);
        __syncthreads();
    }

    int g = lane >> 2, c2 = (lane & 3) * 2;
    #pragma unroll
    for (int mi = 0; mi < 2; mi++) {
        int ra = bm0 + wm + mi * 16 + g;
        #pragma unroll
        for (int nj = 0; nj < 8; nj++) {
            int col = wn + nj * 8 + c2;
            *(float2*)&Opar[(size_t)ra * DIM + col] =
                make_float2(acc[mi][nj][0], acc[mi][nj][1]);
            *(float2*)&Opar[(size_t)(ra + 8) * DIM + col] =
                make_float2(acc[mi][nj][2], acc[mi][nj][3]);
        }
    }
}

// ---------------------------------------------------------------------------
// K6: O = (Opar0 + Opar1) / rowsum.  Block = 4 rows; reduces the 64 psum
// partials per row in-block (rowinv kernel folded in).
// ---------------------------------------------------------------------------
__global__ __launch_bounds__(256) void k_combine(float* __restrict__ C)
{
    __shared__ float sred[8];
    __shared__ float srinv[4];
    int t = threadIdx.x;
    int rowbase = blockIdx.x * 4;

    // reduce psum: warp w covers row (w>>1), half (w&1) of the 64 partials
    float p = g_psum[(size_t)(t & 63) * NROW + rowbase + (t >> 6)];
    #pragma unroll
    for (int o = 16; o; o >>= 1) p += __shfl_xor_sync(0xFFFFFFFFu, p, o);
    if ((t & 31) == 0) sred[t >> 5] = p;
    __syncthreads();
    if (t < 4) srinv[t] = 1.0f / (sred[2 * t] + sred[2 * t + 1]);
    __syncthreads();

    size_t idx = (size_t)blockIdx.x * 256 + t;     // float4 index
    float4 a = ((const float4*)g_Opar[0])[idx];
    float4 b = ((const float4*)g_Opar[1])[idx];
    float r = srinv[t >> 6];
    ((float4*)C)[idx] = make_float4((a.x + b.x) * r, (a.y + b.y) * r,
                                    (a.z + b.z) * r, (a.w + b.w) * r);
}

// ---------------------------------------------------------------------------
extern "C" void kernel_launch(void* const* d_in, const int* in_sizes, int n_in,
                              void* d_out, int out_size)
{
    const float* emb = (const float*)d_in[0];
    float* out = (float*)d_out;

    cudaFuncSetAttribute(k_gemm_s, cudaFuncAttributeMaxDynamicSharedMemorySize, 2 * SMSTAGE);
    cudaFuncSetAttribute(k_gemm_o, cudaFuncAttributeMaxDynamicSharedMemorySize, 2 * OSTG);

    k_normalize<<<NROW / 4, 128>>>(emb);

    dim3 tb(32, 8);
    k_transpose<<<dim3(NROW / 32, DIM / 32), tb>>>(emb);

    k_gemm_s<<<2080, 256, 2 * SMSTAGE>>>();

    k_gemm_o<<<dim3(2, NROW / 64), 256, 2 * OSTG>>>();

    k_combine<<<NROW / 4, 256>>>(out);
}